// round 6
// baseline (speedup 1.0000x reference)
#include <cuda_runtime.h>
#include <cstdint>

#define CIN 128
#define COUT 256
#define HH 64
#define WW 64
#define KTOP 64
#define NOISE_SCALE (8.0f/255.0f)

#define NSTG 72              // K = 1152 = 72 chunks of 16
#define KC2 16
#define ROWP 20              // padded smem row (floats)
#define BAND 4e-3f
#define LISTCAP 320

// ---- smem layout (floats) ----
#define AS_BASE 0            // [stage2][split2][m128][ROWP] = 10240
#define BS_BASE 10240        // [stage2][split2][n256][ROWP] = 20480 -> ends 30720
#define OS_STRIDE 258
#define OS_F (128*OS_STRIDE) // 33024 (overlays AS+BS in epilogue)
#define RB_F 33024
#define WB_F (RB_F+256)
#define TK_F (WB_F+256)
#define CNT_F (TK_F+128)
#define LIST_F (CNT_F+4)
#define SMEM_F (LIST_F+LISTCAP)
#define SMEM_BYTES (SMEM_F*4)

__device__ float g_wsp[NSTG * 2 * COUT * KC2];   // [chunk][split][co][16 permuted]
__device__ float g_wbias[COUT];

__device__ __forceinline__ float tf32_rna(float v) {
    float r;
    asm("cvt.rna.tf32.f32 %0, %1;" : "=f"(r) : "f"(v));
    return r;
}
__device__ __forceinline__ uint32_t smem_to_u32(const void* p) {
    uint32_t a;
    asm("{ .reg .u64 t; cvta.to.shared.u64 t, %1; cvt.u32.u64 %0, t; }" : "=r"(a) : "l"(p));
    return a;
}

#define MMA_TF32(dv, a0, a1, a2, a3, b0, b1) \
    asm volatile("mma.sync.aligned.m16n8k8.row.col.f32.tf32.tf32.f32 " \
        "{%0,%1,%2,%3}, {%4,%5,%6,%7}, {%8,%9}, {%0,%1,%2,%3};" \
        : "+f"((dv)[0]), "+f"((dv)[1]), "+f"((dv)[2]), "+f"((dv)[3]) \
        : "r"(a0), "r"(a1), "r"(a2), "r"(a3), "r"(b0), "r"(b1))

#define CP_ASYNC16(dst_u32, src_ptr) \
    asm volatile("cp.async.ca.shared.global [%0], [%1], 16;" :: "r"(dst_u32), "l"(src_ptr))
#define CP_COMMIT()  asm volatile("cp.async.commit_group;")
#define CP_WAIT0()   asm volatile("cp.async.wait_group 0;" ::: "memory")

__device__ __forceinline__ int as_idx(int stg, int sp, int m, int col) {
    return ((stg * 2 + sp) * 128 + m) * ROWP + col;
}
__device__ __forceinline__ int bs_idx(int stg, int sp, int n, int col) {
    return BS_BASE + ((stg * 2 + sp) * 256 + n) * ROWP + col;
}
__device__ __forceinline__ unsigned f2key(float v) {
    unsigned u = __float_as_uint(v);
    return (u & 0x80000000u) ? ~u : (u | 0x80000000u);
}
__device__ __forceinline__ float key2f(unsigned k) {
    unsigned u = (k & 0x80000000u) ? (k & 0x7fffffffu) : ~k;
    return __uint_as_float(u);
}

// ---------------- prep kernels ----------------
// k permuted within 8-group: pos = (k&3)*2 + ((k>>2)&1)  -> (tig, tig+4) adjacent
__global__ void prep_wsplit(const float* __restrict__ w) {
    int co = blockIdx.x;
    for (int k = threadIdx.x; k < 1152; k += 128) {
        float v = w[co * 1152 + k];
        int c = k >> 4, j = k & 15, w8 = j & 7;
        int col = (j >> 3) * 8 + (w8 & 3) * 2 + (w8 >> 2);
        float hi = tf32_rna(v);
        float lo = tf32_rna(v - hi);
        g_wsp[((c * 2 + 0) * COUT + co) * KC2 + col] = hi;
        g_wsp[((c * 2 + 1) * COUT + co) * KC2 + col] = lo;
    }
}
__global__ void prep_bias(const float* __restrict__ w) {
    __shared__ float red[128];
    int co = blockIdx.x;
    float s = 0.f;
    for (int j = threadIdx.x; j < 1152; j += 128) s += fabsf(w[co * 1152 + j]);
    red[threadIdx.x] = s;
    __syncthreads();
    for (int off = 64; off > 0; off >>= 1) {
        if (threadIdx.x < off) red[threadIdx.x] += red[threadIdx.x + off];
        __syncthreads();
    }
    if (threadIdx.x == 0) g_wbias[co] = red[0];
}

// ---------------- main fused kernel ----------------
__global__ void __launch_bounds__(256, 1)
conv_mma_kernel(const float* __restrict__ x, const float* __restrict__ w,
                const float* __restrict__ rbias,
                const float* __restrict__ noise, float* __restrict__ out) {
    extern __shared__ float smem[];
    const uint32_t smem_base = smem_to_u32(smem);
    const int t   = threadIdx.x;
    const int wid = t >> 5;
    const int lid = t & 31;
    const int g   = lid >> 2;
    const int tig = lid & 3;
    const int b   = blockIdx.y;
    const int y0  = blockIdx.x * 2;

    const int m_base = (wid & 1) * 64;
    const int n_base = (wid >> 1) * 64;

    float* rb_s = smem + RB_F;
    float* wb_s = smem + WB_F;
    unsigned* tkey_s = (unsigned*)(smem + TK_F);
    int* cnt_s = (int*)(smem + CNT_F);
    int* list_s = (int*)(smem + LIST_F);
    rb_s[t] = rbias[t];
    wb_s[t] = g_wbias[t];
    if (t == 0) cnt_s[0] = 0;

    float d[4][8][4];
#pragma unroll
    for (int i = 0; i < 4; i++)
#pragma unroll
        for (int j = 0; j < 8; j++)
#pragma unroll
            for (int q = 0; q < 4; q++) d[i][j][q] = 0.f;

    const int am = t & 127;
    const int jh = t >> 7;

    // ---- prologue: stage 0
    {
        const float4* bsrc = (const float4*)g_wsp;
#pragma unroll
        for (int it = 0; it < 8; it++) {
            int i = it * 256 + t;
            int split = i >> 10, co = (i >> 2) & 255, q = i & 3;
            CP_ASYNC16(smem_base + (uint32_t)bs_idx(0, split, co, q * 4) * 4, bsrc + i);
        }
        CP_COMMIT();
#pragma unroll
        for (int jj = 0; jj < 8; jj++) {
            int j = jh + 2 * jj;
            int k = j;
            int ci = (k * 7282) >> 16;
            int r9 = k - 9 * ci;
            int kh = (r9 * 11) >> 5;
            int kw = r9 - 3 * kh;
            int y  = y0 + (am >> 6) + kh - 1;
            int xx = (am & 63) + kw - 1;
            float v = ((unsigned)y < HH && (unsigned)xx < WW)
                      ? x[((b * CIN + ci) << 12) + (y << 6) + xx] : 0.f;
            int w8 = j & 7;
            int col = (j >> 3) * 8 + (w8 & 3) * 2 + (w8 >> 2);
            float hi = tf32_rna(v);
            smem[as_idx(0, 0, am, col)] = hi;
            smem[as_idx(0, 1, am, col)] = tf32_rna(v - hi);
        }
        CP_WAIT0();
        __syncthreads();
    }

    for (int c = 0; c < NSTG; c++) {
        const int cur = c & 1, nxt = cur ^ 1;
        const bool pf = (c < NSTG - 1);
        if (pf) {
            const float4* bsrc = (const float4*)(g_wsp + (size_t)(c + 1) * 2 * COUT * KC2);
#pragma unroll
            for (int it = 0; it < 8; it++) {
                int i = it * 256 + t;
                int split = i >> 10, co = (i >> 2) & 255, q = i & 3;
                CP_ASYNC16(smem_base + (uint32_t)bs_idx(nxt, split, co, q * 4) * 4, bsrc + i);
            }
            CP_COMMIT();
        }
        float araw[8];
        if (pf) {
#pragma unroll
            for (int jj = 0; jj < 8; jj++) {
                int j = jh + 2 * jj;
                int k = (c + 1) * KC2 + j;
                int ci = (k * 7282) >> 16;
                int r9 = k - 9 * ci;
                int kh = (r9 * 11) >> 5;
                int kw = r9 - 3 * kh;
                int y  = y0 + (am >> 6) + kh - 1;
                int xx = (am & 63) + kw - 1;
                araw[jj] = ((unsigned)y < HH && (unsigned)xx < WW)
                           ? x[((b * CIN + ci) << 12) + (y << 6) + xx] : 0.f;
            }
        }
#pragma unroll
        for (int ks = 0; ks < 2; ks++) {
            const int colk = ks * 8 + tig * 2;
            uint2 ah[4][2], al[4][2];
#pragma unroll
            for (int mt = 0; mt < 4; mt++) {
                int m = m_base + mt * 16 + g;
                ah[mt][0] = *(const uint2*)&smem[as_idx(cur, 0, m,     colk)];
                ah[mt][1] = *(const uint2*)&smem[as_idx(cur, 0, m + 8, colk)];
                al[mt][0] = *(const uint2*)&smem[as_idx(cur, 1, m,     colk)];
                al[mt][1] = *(const uint2*)&smem[as_idx(cur, 1, m + 8, colk)];
            }
#pragma unroll
            for (int nt = 0; nt < 8; nt++) {
                int n = n_base + nt * 8 + g;
                uint2 bh = *(const uint2*)&smem[bs_idx(cur, 0, n, colk)];
                uint2 bl = *(const uint2*)&smem[bs_idx(cur, 1, n, colk)];
#pragma unroll
                for (int mt = 0; mt < 4; mt++) {
                    MMA_TF32(d[mt][nt], ah[mt][0].x, ah[mt][1].x, ah[mt][0].y, ah[mt][1].y, bh.x, bh.y);
                    MMA_TF32(d[mt][nt], ah[mt][0].x, ah[mt][1].x, ah[mt][0].y, ah[mt][1].y, bl.x, bl.y);
                    MMA_TF32(d[mt][nt], al[mt][0].x, al[mt][1].x, al[mt][0].y, al[mt][1].y, bh.x, bh.y);
                }
            }
        }
        if (pf) {
#pragma unroll
            for (int jj = 0; jj < 8; jj++) {
                int j = jh + 2 * jj;
                int w8 = j & 7;
                int col = (j >> 3) * 8 + (w8 & 3) * 2 + (w8 >> 2);
                float hi = tf32_rna(araw[jj]);
                smem[as_idx(nxt, 0, am, col)] = hi;
                smem[as_idx(nxt, 1, am, col)] = tf32_rna(araw[jj] - hi);
            }
            CP_WAIT0();
        }
        __syncthreads();
    }

    // ---- epilogue: spill accums to o_s[p*258 + co]
    float* o_s = smem;
#pragma unroll
    for (int mt = 0; mt < 4; mt++) {
#pragma unroll
        for (int nt = 0; nt < 8; nt++) {
            int m  = m_base + mt * 16 + g;
            int co = n_base + nt * 8 + 2 * tig;
            *(float2*)&o_s[m * OS_STRIDE + co]       = make_float2(d[mt][nt][0], d[mt][nt][1]);
            *(float2*)&o_s[(m + 8) * OS_STRIDE + co] = make_float2(d[mt][nt][2], d[mt][nt][3]);
        }
    }
    __syncthreads();

    // ---- noise inject
#pragma unroll 4
    for (int it = 0; it < 128; it++) {
        int i  = it * 256 + t;
        int co = i >> 7;
        int p  = i & 127;
        float u = noise[((b * COUT + co) << 12) + (y0 << 6) + p];
        o_s[p * OS_STRIDE + co] += wb_s[co] * (NOISE_SCALE * (2.f * u - 1.f));
    }
    __syncthreads();

    // ---- pass 1: approximate 64th-largest per position (binary search on keys)
    for (int ii = 0; ii < 8; ii++) {
        int pa = wid * 16 + ii * 2;
        int pb = pa + 1;
        unsigned ka[8], kb[8];
#pragma unroll
        for (int m = 0; m < 8; m++) {
            ka[m] = f2key(o_s[pa * OS_STRIDE + lid + 32 * m]);
            kb[m] = f2key(o_s[pb * OS_STRIDE + lid + 32 * m]);
        }
        unsigned ra = 0u, rb2 = 0u;
        for (int bit = 31; bit >= 0; bit--) {
            unsigned ca_ = ra  | (1u << bit);
            unsigned cb_ = rb2 | (1u << bit);
            unsigned na = 0, nb = 0;
#pragma unroll
            for (int m = 0; m < 8; m++) { na += (ka[m] >= ca_); nb += (kb[m] >= cb_); }
            na = __reduce_add_sync(0xffffffffu, na);
            nb = __reduce_add_sync(0xffffffffu, nb);
            if (na >= KTOP) ra  = ca_;
            if (nb >= KTOP) rb2 = cb_;
        }
        if (lid == 0) { tkey_s[pa] = ra; tkey_s[pb] = rb2; }
    }
    __syncthreads();

    // ---- band scan: collect elements within BAND of the approx threshold
#pragma unroll 4
    for (int it = 0; it < 128; it++) {
        int i  = it * 256 + t;
        int co = i >> 7;
        int p  = i & 127;
        float v  = o_s[p * OS_STRIDE + co];
        float tv = key2f(tkey_s[p]);
        if (fabsf(v - tv) < BAND) {
            int idx = atomicAdd(cnt_s, 1);
            if (idx < LISTCAP) list_s[idx] = (p << 8) | co;
        }
    }
    __syncthreads();

    // ---- exact fp32 recompute of band elements (one warp per element)
    {
        int cnt = min(cnt_s[0], LISTCAP);
        for (int e = wid; e < cnt; e += 8) {
            int pc = list_s[e];
            int p  = pc >> 8;
            int co = pc & 255;
            float acc = 0.f;
#pragma unroll
            for (int j = 0; j < 36; j++) {
                int k = lid + 32 * j;
                int ci = (k * 7282) >> 16;
                int r9 = k - 9 * ci;
                int kh = (r9 * 11) >> 5;
                int kw = r9 - 3 * kh;
                int y  = y0 + (p >> 6) + kh - 1;
                int xx = (p & 63) + kw - 1;
                float xv = ((unsigned)y < HH && (unsigned)xx < WW)
                           ? x[((b * CIN + ci) << 12) + (y << 6) + xx] : 0.f;
                acc += xv * w[co * 1152 + k];
            }
#pragma unroll
            for (int off = 16; off > 0; off >>= 1)
                acc += __shfl_xor_sync(0xffffffffu, acc, off);
            if (lid == 0) {
                float u = noise[((b * COUT + co) << 12) + (y0 << 6) + p];
                o_s[p * OS_STRIDE + co] = acc + wb_s[co] * (NOISE_SCALE * (2.f * u - 1.f));
            }
        }
    }
    __syncthreads();

    // ---- pass 2: exact 64th-largest on corrected values
    for (int ii = 0; ii < 8; ii++) {
        int pa = wid * 16 + ii * 2;
        int pb = pa + 1;
        unsigned ka[8], kb[8];
#pragma unroll
        for (int m = 0; m < 8; m++) {
            ka[m] = f2key(o_s[pa * OS_STRIDE + lid + 32 * m]);
            kb[m] = f2key(o_s[pb * OS_STRIDE + lid + 32 * m]);
        }
        unsigned ra = 0u, rb2 = 0u;
        for (int bit = 31; bit >= 0; bit--) {
            unsigned ca_ = ra  | (1u << bit);
            unsigned cb_ = rb2 | (1u << bit);
            unsigned na = 0, nb = 0;
#pragma unroll
            for (int m = 0; m < 8; m++) { na += (ka[m] >= ca_); nb += (kb[m] >= cb_); }
            na = __reduce_add_sync(0xffffffffu, na);
            nb = __reduce_add_sync(0xffffffffu, nb);
            if (na >= KTOP) ra  = ca_;
            if (nb >= KTOP) rb2 = cb_;
        }
        if (lid == 0) { tkey_s[pa] = ra; tkey_s[pb] = rb2; }
    }
    __syncthreads();

    // ---- threshold (>= keeps ties) + relu_bias + relu, coalesced store
#pragma unroll 4
    for (int it = 0; it < 128; it++) {
        int i  = it * 256 + t;
        int co = i >> 7;
        int p  = i & 127;
        float v = o_s[p * OS_STRIDE + co];
        float r = (f2key(v) >= tkey_s[p]) ? v : 0.f;
        r = fmaxf(r + rb_s[co], 0.f);
        out[((b * COUT + co) << 12) + (y0 << 6) + p] = r;
    }
}

extern "C" void kernel_launch(void* const* d_in, const int* in_sizes, int n_in,
                              void* d_out, int out_size) {
    const float* x  = (const float*)d_in[0];
    const float* w  = (const float*)d_in[1];
    const float* rb = (const float*)d_in[2];
    const float* nu = (const float*)d_in[3];
    float* out = (float*)d_out;

    cudaFuncSetAttribute(conv_mma_kernel,
                         cudaFuncAttributeMaxDynamicSharedMemorySize, SMEM_BYTES);

    prep_wsplit<<<256, 128>>>(w);
    prep_bias<<<256, 128>>>(w);
    conv_mma_kernel<<<dim3(32, 32), 256, SMEM_BYTES>>>(x, w, rb, nu, out);
}

// round 9
// speedup vs baseline: 1.5108x; 1.5108x over previous
#include <cuda_runtime.h>
#include <cuda_bf16.h>
#include <cstdint>

#define CIN 128
#define COUT 256
#define HH 64
#define WW 64
#define KTOP 64
#define NOISE_SCALE (8.0f/255.0f)

#define NSTG 72              // K = 1152 = 72 chunks of 16
#define BAND 1e-3f
#define LISTCAP 384

// ---- smem layout ----
// A: [stage2][split2][128 pix][32B]  = 16384 B  at 0
// B: [stage2][split2][256 ch ][32B]  = 32768 B  at 16384   (end 49152)
// o_s overlay: 128*258 floats = 132096 B at 0  (stride 258: even, so
// float2 spills at [p*258 + even co] stay 8B-aligned)
#define AS_B 0
#define BS_B 16384
#define OS_STRIDE 258
#define RB_F 33024
#define WB_F (RB_F+256)
#define TK_F (WB_F+256)
#define CNT_F (TK_F+128)
#define LIST_F (CNT_F+4)
#define SMEM_F (LIST_F+LISTCAP)
#define SMEM_BYTES (SMEM_F*4)

// prepped weights: [chunk][split][co][q0..q3] as uint2 (4 bf16 per 8B word)
// word q holds k = {2q, 2q+1} (.x) and {2q+8, 2q+9} (.y)
__device__ uint2 g_wsp[NSTG * 2 * COUT * 4];
__device__ float g_wbias[COUT];

__device__ __forceinline__ uint32_t smem_to_u32(const void* p) {
    uint32_t a;
    asm("{ .reg .u64 t; cvta.to.shared.u64 t, %1; cvt.u32.u64 %0, t; }" : "=r"(a) : "l"(p));
    return a;
}
__device__ __forceinline__ unsigned f2key(float v) {
    unsigned u = __float_as_uint(v);
    return (u & 0x80000000u) ? ~u : (u | 0x80000000u);
}
__device__ __forceinline__ float key2f(unsigned k) {
    unsigned u = (k & 0x80000000u) ? (k & 0x7fffffffu) : ~k;
    return __uint_as_float(u);
}
__device__ __forceinline__ void splitbf(float v, unsigned& h, unsigned& l) {
    __nv_bfloat16 hb = __float2bfloat16(v);
    float hf = __bfloat162float(hb);
    __nv_bfloat16 lb = __float2bfloat16(v - hf);
    h = (unsigned)*(unsigned short*)&hb;
    l = (unsigned)*(unsigned short*)&lb;
}

#define MMA_BF16(dv, a0, a1, a2, a3, b0, b1) \
    asm volatile("mma.sync.aligned.m16n8k16.row.col.f32.bf16.bf16.f32 " \
        "{%0,%1,%2,%3}, {%4,%5,%6,%7}, {%8,%9}, {%0,%1,%2,%3};" \
        : "+f"((dv)[0]), "+f"((dv)[1]), "+f"((dv)[2]), "+f"((dv)[3]) \
        : "r"(a0), "r"(a1), "r"(a2), "r"(a3), "r"(b0), "r"(b1))

#define CP_ASYNC16(dst_u32, src_ptr) \
    asm volatile("cp.async.ca.shared.global [%0], [%1], 16;" :: "r"(dst_u32), "l"(src_ptr))
#define CP_COMMIT()  asm volatile("cp.async.commit_group;")
#define CP_WAIT0()   asm volatile("cp.async.wait_group 0;" ::: "memory")

__device__ __forceinline__ int a_addr(int stg, int sp, int p, int q) {
    return AS_B + ((stg * 2 + sp) * 128 + p) * 32 + q * 8;
}
__device__ __forceinline__ int b_addr(int stg, int sp, int n, int q) {
    return BS_B + ((stg * 2 + sp) * 256 + n) * 32 + q * 8;
}

// ---------------- prep kernels ----------------
__global__ void prep_wsplit(const float* __restrict__ w) {
    int co = blockIdx.x;
    unsigned short* dst = (unsigned short*)g_wsp;
    for (int k = threadIdx.x; k < 1152; k += 128) {
        float v = w[co * 1152 + k];
        int c = k >> 4, j = k & 15;
        int q = (j & 7) >> 1, half = j >> 3, slot = j & 1;
        unsigned h, l;
        splitbf(v, h, l);
        int base0 = (((c * 2 + 0) * COUT + co) * 4 + q) * 4 + half * 2 + slot;
        int base1 = (((c * 2 + 1) * COUT + co) * 4 + q) * 4 + half * 2 + slot;
        dst[base0] = (unsigned short)h;
        dst[base1] = (unsigned short)l;
    }
}
__global__ void prep_bias(const float* __restrict__ w) {
    __shared__ float red[128];
    int co = blockIdx.x;
    float s = 0.f;
    for (int j = threadIdx.x; j < 1152; j += 128) s += fabsf(w[co * 1152 + j]);
    red[threadIdx.x] = s;
    __syncthreads();
    for (int off = 64; off > 0; off >>= 1) {
        if (threadIdx.x < off) red[threadIdx.x] += red[threadIdx.x + off];
        __syncthreads();
    }
    if (threadIdx.x == 0) g_wbias[co] = red[0];
}

// ---------------- main fused kernel ----------------
// CTA: 128 pixels (2 rows x 64) x 256 couts, 512 threads (16 warps).
// warp (wm = wid&3, wn = wid>>2): tile 32 pixels x 64 couts = 2 m-tiles x 8 n-tiles
// of m16n8k16 bf16, 3 passes (hh, hl, lh) per k16 chunk.
__global__ void __launch_bounds__(512, 1)
conv_mma_kernel(const float* __restrict__ x, const float* __restrict__ w,
                const float* __restrict__ rbias,
                const float* __restrict__ noise, float* __restrict__ out) {
    extern __shared__ float smem[];
    char* smc = (char*)smem;
    const uint32_t smem_base = smem_to_u32(smem);
    const int t   = threadIdx.x;
    const int wid = t >> 5;
    const int lid = t & 31;
    const int g   = lid >> 2;
    const int tig = lid & 3;
    const int b   = blockIdx.y;
    const int y0  = blockIdx.x * 2;

    const int wm = wid & 3;
    const int wn = wid >> 2;

    float* rb_s = smem + RB_F;
    float* wb_s = smem + WB_F;
    unsigned* tkey_s = (unsigned*)(smem + TK_F);
    int* cnt_s = (int*)(smem + CNT_F);
    int* list_s = (int*)(smem + LIST_F);
    if (t < 256) { rb_s[t] = rbias[t]; wb_s[t] = g_wbias[t]; }
    if (t == 0) cnt_s[0] = 0;

    float d[2][8][4];
#pragma unroll
    for (int i = 0; i < 2; i++)
#pragma unroll
        for (int j = 0; j < 8; j++)
#pragma unroll
            for (int q = 0; q < 4; q++) d[i][j][q] = 0.f;

    const int ap  = t >> 2;      // A-build pixel 0..127
    const int aq  = t & 3;       // A-build q group
    const int apy = ap >> 6;
    const int apx = ap & 63;

    // ---- prologue: stage 0
    {
        const char* bsrc = (const char*)g_wsp;
#pragma unroll
        for (int it = 0; it < 2; it++) {
            int i = it * 512 + t;                 // 16B unit 0..1023
            CP_ASYNC16(smem_base + (uint32_t)(BS_B + i * 16), bsrc + i * 16);
        }
        CP_COMMIT();
        float v[4];
#pragma unroll
        for (int j = 0; j < 4; j++) {
            int k = 2 * aq + (j & 1) + (j >> 1) * 8;
            int ci = (k * 7282) >> 16;
            int r9 = k - 9 * ci;
            int kh = (r9 * 11) >> 5;
            int kw = r9 - 3 * kh;
            int y  = y0 + apy + kh - 1;
            int xx = apx + kw - 1;
            v[j] = ((unsigned)y < HH && (unsigned)xx < WW)
                   ? x[((b * CIN + ci) << 12) + (y << 6) + xx] : 0.f;
        }
        unsigned h0, l0, h1, l1, h2, l2, h3, l3;
        splitbf(v[0], h0, l0); splitbf(v[1], h1, l1);
        splitbf(v[2], h2, l2); splitbf(v[3], h3, l3);
        *(uint2*)(smc + a_addr(0, 0, ap, aq)) = make_uint2(h0 | (h1 << 16), h2 | (h3 << 16));
        *(uint2*)(smc + a_addr(0, 1, ap, aq)) = make_uint2(l0 | (l1 << 16), l2 | (l3 << 16));
        CP_WAIT0();
        __syncthreads();
    }

    for (int c = 0; c < NSTG; c++) {
        const int cur = c & 1, nxt = cur ^ 1;
        const bool pf = (c < NSTG - 1);
        // ---- issue next B via cp.async
        if (pf) {
            const char* bsrc = (const char*)(g_wsp + (size_t)(c + 1) * 2 * COUT * 4);
#pragma unroll
            for (int it = 0; it < 2; it++) {
                int i = it * 512 + t;
                CP_ASYNC16(smem_base + (uint32_t)(BS_B + nxt * 16384 + i * 16), bsrc + i * 16);
            }
            CP_COMMIT();
        }
        // ---- prefetch next A raw
        float v[4];
        if (pf) {
#pragma unroll
            for (int j = 0; j < 4; j++) {
                int k = (c + 1) * 16 + 2 * aq + (j & 1) + (j >> 1) * 8;
                int ci = (k * 7282) >> 16;
                int r9 = k - 9 * ci;
                int kh = (r9 * 11) >> 5;
                int kw = r9 - 3 * kh;
                int y  = y0 + apy + kh - 1;
                int xx = apx + kw - 1;
                v[j] = ((unsigned)y < HH && (unsigned)xx < WW)
                       ? x[((b * CIN + ci) << 12) + (y << 6) + xx] : 0.f;
            }
        }
        // ---- compute: load A frags once, sweep 8 n-tiles x 2 m-tiles x 3 passes
        {
            uint2 ah[2][2], al[2][2];
#pragma unroll
            for (int mt = 0; mt < 2; mt++) {
                int m0 = wm * 32 + mt * 16 + g;
                ah[mt][0] = *(const uint2*)(smc + a_addr(cur, 0, m0,     tig));
                ah[mt][1] = *(const uint2*)(smc + a_addr(cur, 0, m0 + 8, tig));
                al[mt][0] = *(const uint2*)(smc + a_addr(cur, 1, m0,     tig));
                al[mt][1] = *(const uint2*)(smc + a_addr(cur, 1, m0 + 8, tig));
            }
#pragma unroll
            for (int nt = 0; nt < 8; nt++) {
                int n = wn * 64 + nt * 8 + g;
                uint2 bh = *(const uint2*)(smc + b_addr(cur, 0, n, tig));
                uint2 bl = *(const uint2*)(smc + b_addr(cur, 1, n, tig));
#pragma unroll
                for (int mt = 0; mt < 2; mt++) {
                    MMA_BF16(d[mt][nt], ah[mt][0].x, ah[mt][1].x, ah[mt][0].y, ah[mt][1].y, bh.x, bh.y);
                    MMA_BF16(d[mt][nt], ah[mt][0].x, ah[mt][1].x, ah[mt][0].y, ah[mt][1].y, bl.x, bl.y);
                    MMA_BF16(d[mt][nt], al[mt][0].x, al[mt][1].x, al[mt][0].y, al[mt][1].y, bh.x, bh.y);
                }
            }
        }
        // ---- store next A, drain, sync
        if (pf) {
            unsigned h0, l0, h1, l1, h2, l2, h3, l3;
            splitbf(v[0], h0, l0); splitbf(v[1], h1, l1);
            splitbf(v[2], h2, l2); splitbf(v[3], h3, l3);
            *(uint2*)(smc + a_addr(nxt, 0, ap, aq)) = make_uint2(h0 | (h1 << 16), h2 | (h3 << 16));
            *(uint2*)(smc + a_addr(nxt, 1, ap, aq)) = make_uint2(l0 | (l1 << 16), l2 | (l3 << 16));
            CP_WAIT0();
        }
        __syncthreads();
    }

    // ---- epilogue: spill accums to o_s[p*258 + co]  (even stride -> aligned float2)
    float* o_s = smem;
#pragma unroll
    for (int mt = 0; mt < 2; mt++) {
#pragma unroll
        for (int nt = 0; nt < 8; nt++) {
            int p  = wm * 32 + mt * 16 + g;
            int co = wn * 64 + nt * 8 + 2 * tig;
            *(float2*)&o_s[p * OS_STRIDE + co]       = make_float2(d[mt][nt][0], d[mt][nt][1]);
            *(float2*)&o_s[(p + 8) * OS_STRIDE + co] = make_float2(d[mt][nt][2], d[mt][nt][3]);
        }
    }
    __syncthreads();

    // ---- noise inject (coalesced: p 0..127 = 2 contiguous gmem rows)
#pragma unroll 4
    for (int it = 0; it < 64; it++) {
        int i  = it * 512 + t;
        int co = i >> 7;
        int p  = i & 127;
        float u = noise[((b * COUT + co) << 12) + (y0 << 6) + p];
        o_s[p * OS_STRIDE + co] += wb_s[co] * (NOISE_SCALE * (2.f * u - 1.f));
    }
    __syncthreads();

    // ---- pass 1: approx 64th-largest per pixel (dual interleaved binary search)
    for (int ii = 0; ii < 4; ii++) {
        int pa = wid * 8 + ii * 2;
        int pb = pa + 1;
        unsigned ka[8], kb[8];
#pragma unroll
        for (int m = 0; m < 8; m++) {
            ka[m] = f2key(o_s[pa * OS_STRIDE + lid + 32 * m]);
            kb[m] = f2key(o_s[pb * OS_STRIDE + lid + 32 * m]);
        }
        unsigned ra = 0u, rb2 = 0u;
        for (int bit = 31; bit >= 0; bit--) {
            unsigned ca_ = ra  | (1u << bit);
            unsigned cb_ = rb2 | (1u << bit);
            unsigned na = 0, nb = 0;
#pragma unroll
            for (int m = 0; m < 8; m++) { na += (ka[m] >= ca_); nb += (kb[m] >= cb_); }
            na = __reduce_add_sync(0xffffffffu, na);
            nb = __reduce_add_sync(0xffffffffu, nb);
            if (na >= KTOP) ra  = ca_;
            if (nb >= KTOP) rb2 = cb_;
        }
        if (lid == 0) { tkey_s[pa] = ra; tkey_s[pb] = rb2; }
    }
    __syncthreads();

    // ---- band scan: elements within BAND of approx threshold
#pragma unroll 4
    for (int it = 0; it < 64; it++) {
        int i  = it * 512 + t;
        int co = i >> 7;
        int p  = i & 127;
        float vv = o_s[p * OS_STRIDE + co];
        float tv = key2f(tkey_s[p]);
        if (fabsf(vv - tv) < BAND) {
            int idx = atomicAdd(cnt_s, 1);
            if (idx < LISTCAP) list_s[idx] = (p << 8) | co;
        }
    }
    __syncthreads();

    // ---- exact fp32 recompute of band elements (one warp per element)
    {
        int cnt = min(cnt_s[0], LISTCAP);
        for (int e = wid; e < cnt; e += 16) {
            int pc = list_s[e];
            int p  = pc >> 8;
            int co = pc & 255;
            float acc = 0.f;
#pragma unroll
            for (int j = 0; j < 36; j++) {
                int k = lid + 32 * j;
                int ci = (k * 7282) >> 16;
                int r9 = k - 9 * ci;
                int kh = (r9 * 11) >> 5;
                int kw = r9 - 3 * kh;
                int y  = y0 + (p >> 6) + kh - 1;
                int xx = (p & 63) + kw - 1;
                float xv = ((unsigned)y < HH && (unsigned)xx < WW)
                           ? x[((b * CIN + ci) << 12) + (y << 6) + xx] : 0.f;
                acc += xv * w[co * 1152 + k];
            }
#pragma unroll
            for (int off = 16; off > 0; off >>= 1)
                acc += __shfl_xor_sync(0xffffffffu, acc, off);
            if (lid == 0) {
                float u = noise[((b * COUT + co) << 12) + (y0 << 6) + p];
                o_s[p * OS_STRIDE + co] = acc + wb_s[co] * (NOISE_SCALE * (2.f * u - 1.f));
            }
        }
    }
    __syncthreads();

    // ---- pass 2: exact 64th-largest on corrected values
    for (int ii = 0; ii < 4; ii++) {
        int pa = wid * 8 + ii * 2;
        int pb = pa + 1;
        unsigned ka[8], kb[8];
#pragma unroll
        for (int m = 0; m < 8; m++) {
            ka[m] = f2key(o_s[pa * OS_STRIDE + lid + 32 * m]);
            kb[m] = f2key(o_s[pb * OS_STRIDE + lid + 32 * m]);
        }
        unsigned ra = 0u, rb2 = 0u;
        for (int bit = 31; bit >= 0; bit--) {
            unsigned ca_ = ra  | (1u << bit);
            unsigned cb_ = rb2 | (1u << bit);
            unsigned na = 0, nb = 0;
#pragma unroll
            for (int m = 0; m < 8; m++) { na += (ka[m] >= ca_); nb += (kb[m] >= cb_); }
            na = __reduce_add_sync(0xffffffffu, na);
            nb = __reduce_add_sync(0xffffffffu, nb);
            if (na >= KTOP) ra  = ca_;
            if (nb >= KTOP) rb2 = cb_;
        }
        if (lid == 0) { tkey_s[pa] = ra; tkey_s[pb] = rb2; }
    }
    __syncthreads();

    // ---- threshold (>= keeps ties) + relu_bias + relu, coalesced store
#pragma unroll 4
    for (int it = 0; it < 64; it++) {
        int i  = it * 512 + t;
        int co = i >> 7;
        int p  = i & 127;
        float vv = o_s[p * OS_STRIDE + co];
        float r = (f2key(vv) >= tkey_s[p]) ? vv : 0.f;
        r = fmaxf(r + rb_s[co], 0.f);
        out[((b * COUT + co) << 12) + (y0 << 6) + p] = r;
    }
}

extern "C" void kernel_launch(void* const* d_in, const int* in_sizes, int n_in,
                              void* d_out, int out_size) {
    const float* x  = (const float*)d_in[0];
    const float* w  = (const float*)d_in[1];
    const float* rb = (const float*)d_in[2];
    const float* nu = (const float*)d_in[3];
    float* out = (float*)d_out;

    cudaFuncSetAttribute(conv_mma_kernel,
                         cudaFuncAttributeMaxDynamicSharedMemorySize, SMEM_BYTES);

    prep_wsplit<<<256, 128>>>(w);
    prep_bias<<<256, 128>>>(w);
    conv_mma_kernel<<<dim3(32, 32), 512, SMEM_BYTES>>>(x, w, rb, nu, out);
}

// round 10
// speedup vs baseline: 1.8145x; 1.2010x over previous
#include <cuda_runtime.h>
#include <cuda_fp16.h>
#include <cstdint>

#define CIN 128
#define COUT 256
#define HH 64
#define WW 64
#define KTOP 64
#define NOISE_SCALE (8.0f/255.0f)

#define NSTG 36              // K = 1152 = 36 chunks of 32 (2 x k16 halves)
#define BAND 4.5e-3f
#define LISTCAP 512

// ---- smem layout ----
// A: [stage2][ks2][128 pix][32B]  = 16384 B  at 0
// B: [stage2][ks2][256 ch ][32B]  = 32768 B  at 16384   (end 49152)
// o_s overlay: 128*258 floats = 132096 B at 0 (even stride -> aligned float2)
#define AS_B 0
#define BS_B 16384
#define OS_STRIDE 258
#define RB_F 33024
#define WB_F (RB_F+256)
#define TK_F (WB_F+256)
#define CNT_F (TK_F+128)
#define LIST_F (CNT_F+4)
#define SMEM_F (LIST_F+LISTCAP)
#define SMEM_BYTES (SMEM_F*4)

// prepped weights (single fp16): [chunk32][ks2][co][q0..q3] as uint2
// word q holds k16-local k = {2q, 2q+1} (.x) and {2q+8, 2q+9} (.y)
__device__ uint2 g_wh[NSTG * 2 * COUT * 4];
__device__ float g_wbias[COUT];

__device__ __forceinline__ uint32_t smem_to_u32(const void* p) {
    uint32_t a;
    asm("{ .reg .u64 t; cvta.to.shared.u64 t, %1; cvt.u32.u64 %0, t; }" : "=r"(a) : "l"(p));
    return a;
}
__device__ __forceinline__ unsigned f2key(float v) {
    unsigned u = __float_as_uint(v);
    return (u & 0x80000000u) ? ~u : (u | 0x80000000u);
}
__device__ __forceinline__ float key2f(unsigned k) {
    unsigned u = (k & 0x80000000u) ? (k & 0x7fffffffu) : ~k;
    return __uint_as_float(u);
}
__device__ __forceinline__ unsigned h2(float lo, float hi) {
    __half a = __float2half(lo), b = __float2half(hi);
    return (unsigned)__half_as_ushort(a) | ((unsigned)__half_as_ushort(b) << 16);
}

#define MMA_FP16(dv, a0, a1, a2, a3, b0, b1) \
    asm volatile("mma.sync.aligned.m16n8k16.row.col.f32.f16.f16.f32 " \
        "{%0,%1,%2,%3}, {%4,%5,%6,%7}, {%8,%9}, {%0,%1,%2,%3};" \
        : "+f"((dv)[0]), "+f"((dv)[1]), "+f"((dv)[2]), "+f"((dv)[3]) \
        : "r"(a0), "r"(a1), "r"(a2), "r"(a3), "r"(b0), "r"(b1))

#define CP_ASYNC16(dst_u32, src_ptr) \
    asm volatile("cp.async.ca.shared.global [%0], [%1], 16;" :: "r"(dst_u32), "l"(src_ptr))
#define CP_COMMIT()  asm volatile("cp.async.commit_group;")
#define CP_WAIT0()   asm volatile("cp.async.wait_group 0;" ::: "memory")

__device__ __forceinline__ int a_addr(int stg, int ks, int p, int q) {
    return AS_B + ((stg * 2 + ks) * 128 + p) * 32 + q * 8;
}
__device__ __forceinline__ int b_addr(int stg, int ks, int n, int q) {
    return BS_B + ((stg * 2 + ks) * 256 + n) * 32 + q * 8;
}

// ---------------- prep kernels ----------------
__global__ void prep_whalf(const float* __restrict__ w) {
    int co = blockIdx.x;
    unsigned short* dst = (unsigned short*)g_wh;
    for (int k = threadIdx.x; k < 1152; k += 128) {
        float v = w[co * 1152 + k];
        int c = k >> 5, j32 = k & 31;
        int ks = j32 >> 4, j = j32 & 15;
        int q = (j & 7) >> 1, half = j >> 3, slot = j & 1;
        __half hv = __float2half(v);
        int idx = ((((c * 2 + ks) * COUT + co) * 4 + q) * 4) + half * 2 + slot;
        dst[idx] = __half_as_ushort(hv);
    }
}
__global__ void prep_bias(const float* __restrict__ w) {
    __shared__ float red[128];
    int co = blockIdx.x;
    float s = 0.f;
    for (int j = threadIdx.x; j < 1152; j += 128) s += fabsf(w[co * 1152 + j]);
    red[threadIdx.x] = s;
    __syncthreads();
    for (int off = 64; off > 0; off >>= 1) {
        if (threadIdx.x < off) red[threadIdx.x] += red[threadIdx.x + off];
        __syncthreads();
    }
    if (threadIdx.x == 0) g_wbias[co] = red[0];
}

// ---------------- main fused kernel ----------------
// CTA: 128 pixels (2 rows x 64) x 256 couts, 512 threads (16 warps).
// warp (wm = wid&3, wn = wid>>2): tile 32 pixels x 64 couts = 2 m-tiles x 8 n-tiles
// of m16n8k16 fp16, SINGLE pass, 2 k16-halves per stage (chunk = 32 k).
__global__ void __launch_bounds__(512, 1)
conv_mma_kernel(const float* __restrict__ x, const float* __restrict__ w,
                const float* __restrict__ rbias,
                const float* __restrict__ noise, float* __restrict__ out) {
    extern __shared__ float smem[];
    char* smc = (char*)smem;
    const uint32_t smem_base = smem_to_u32(smem);
    const int t   = threadIdx.x;
    const int wid = t >> 5;
    const int lid = t & 31;
    const int g   = lid >> 2;
    const int tig = lid & 3;
    const int b   = blockIdx.y;
    const int y0  = blockIdx.x * 2;

    const int wm = wid & 3;
    const int wn = wid >> 2;

    float* rb_s = smem + RB_F;
    float* wb_s = smem + WB_F;
    unsigned* tkey_s = (unsigned*)(smem + TK_F);
    int* cnt_s = (int*)(smem + CNT_F);
    int* list_s = (int*)(smem + LIST_F);
    if (t < 256) { rb_s[t] = rbias[t]; wb_s[t] = g_wbias[t]; }
    if (t == 0) cnt_s[0] = 0;

    float d[2][8][4];
#pragma unroll
    for (int i = 0; i < 2; i++)
#pragma unroll
        for (int j = 0; j < 8; j++)
#pragma unroll
            for (int q = 0; q < 4; q++) d[i][j][q] = 0.f;

    const int ap  = t >> 2;      // A-build pixel 0..127
    const int aq  = t & 3;       // A-build q group
    const int apy = ap >> 6;
    const int apx = ap & 63;

    // ---- prologue: stage 0
    {
        const char* bsrc = (const char*)g_wh;
#pragma unroll
        for (int it = 0; it < 2; it++) {
            int i = it * 512 + t;                 // 16B unit 0..1023
            CP_ASYNC16(smem_base + (uint32_t)(BS_B + i * 16), bsrc + i * 16);
        }
        CP_COMMIT();
        float v[8];
#pragma unroll
        for (int jj = 0; jj < 8; jj++) {
            int ks = jj >> 2, sub = jj & 3;
            int k = ks * 16 + 2 * aq + (sub & 1) + (sub >> 1) * 8;
            int ci = (k * 7282) >> 16;
            int r9 = k - 9 * ci;
            int kh = (r9 * 11) >> 5;
            int kw = r9 - 3 * kh;
            int y  = y0 + apy + kh - 1;
            int xx = apx + kw - 1;
            v[jj] = ((unsigned)y < HH && (unsigned)xx < WW)
                    ? x[((b * CIN + ci) << 12) + (y << 6) + xx] : 0.f;
        }
        *(uint2*)(smc + a_addr(0, 0, ap, aq)) = make_uint2(h2(v[0], v[1]), h2(v[2], v[3]));
        *(uint2*)(smc + a_addr(0, 1, ap, aq)) = make_uint2(h2(v[4], v[5]), h2(v[6], v[7]));
        CP_WAIT0();
        __syncthreads();
    }

    for (int c = 0; c < NSTG; c++) {
        const int cur = c & 1, nxt = cur ^ 1;
        const bool pf = (c < NSTG - 1);
        // ---- issue next B via cp.async (16KB per stage)
        if (pf) {
            const char* bsrc = (const char*)(g_wh + (size_t)(c + 1) * 2 * COUT * 4);
#pragma unroll
            for (int it = 0; it < 2; it++) {
                int i = it * 512 + t;
                CP_ASYNC16(smem_base + (uint32_t)(BS_B + nxt * 16384 + i * 16), bsrc + i * 16);
            }
            CP_COMMIT();
        }
        // ---- prefetch next A raw (8 values: 2 k16-halves x 4)
        float v[8];
        if (pf) {
#pragma unroll
            for (int jj = 0; jj < 8; jj++) {
                int ks = jj >> 2, sub = jj & 3;
                int k = (c + 1) * 32 + ks * 16 + 2 * aq + (sub & 1) + (sub >> 1) * 8;
                int ci = (k * 7282) >> 16;
                int r9 = k - 9 * ci;
                int kh = (r9 * 11) >> 5;
                int kw = r9 - 3 * kh;
                int y  = y0 + apy + kh - 1;
                int xx = apx + kw - 1;
                v[jj] = ((unsigned)y < HH && (unsigned)xx < WW)
                        ? x[((b * CIN + ci) << 12) + (y << 6) + xx] : 0.f;
            }
        }
        // ---- compute: 2 k16-halves, 2 m-tiles x 8 n-tiles, single fp16 pass
#pragma unroll
        for (int ks = 0; ks < 2; ks++) {
            uint2 af[2][2];
#pragma unroll
            for (int mt = 0; mt < 2; mt++) {
                int m0 = wm * 32 + mt * 16 + g;
                af[mt][0] = *(const uint2*)(smc + a_addr(cur, ks, m0,     tig));
                af[mt][1] = *(const uint2*)(smc + a_addr(cur, ks, m0 + 8, tig));
            }
#pragma unroll
            for (int nt = 0; nt < 8; nt++) {
                int n = wn * 64 + nt * 8 + g;
                uint2 bf_ = *(const uint2*)(smc + b_addr(cur, ks, n, tig));
#pragma unroll
                for (int mt = 0; mt < 2; mt++) {
                    MMA_FP16(d[mt][nt], af[mt][0].x, af[mt][1].x, af[mt][0].y, af[mt][1].y,
                             bf_.x, bf_.y);
                }
            }
        }
        // ---- store next A, drain, sync
        if (pf) {
            *(uint2*)(smc + a_addr(nxt, 0, ap, aq)) = make_uint2(h2(v[0], v[1]), h2(v[2], v[3]));
            *(uint2*)(smc + a_addr(nxt, 1, ap, aq)) = make_uint2(h2(v[4], v[5]), h2(v[6], v[7]));
            CP_WAIT0();
        }
        __syncthreads();
    }

    // ---- epilogue: spill accums to o_s[p*258 + co]
    float* o_s = smem;
#pragma unroll
    for (int mt = 0; mt < 2; mt++) {
#pragma unroll
        for (int nt = 0; nt < 8; nt++) {
            int p  = wm * 32 + mt * 16 + g;
            int co = wn * 64 + nt * 8 + 2 * tig;
            *(float2*)&o_s[p * OS_STRIDE + co]       = make_float2(d[mt][nt][0], d[mt][nt][1]);
            *(float2*)&o_s[(p + 8) * OS_STRIDE + co] = make_float2(d[mt][nt][2], d[mt][nt][3]);
        }
    }
    __syncthreads();

    // ---- noise inject (coalesced: p 0..127 = 2 contiguous gmem rows)
#pragma unroll 4
    for (int it = 0; it < 64; it++) {
        int i  = it * 512 + t;
        int co = i >> 7;
        int p  = i & 127;
        float u = noise[((b * COUT + co) << 12) + (y0 << 6) + p];
        o_s[p * OS_STRIDE + co] += wb_s[co] * (NOISE_SCALE * (2.f * u - 1.f));
    }
    __syncthreads();

    // ---- pass 1: approx 64th-largest per pixel (dual interleaved binary search)
    for (int ii = 0; ii < 4; ii++) {
        int pa = wid * 8 + ii * 2;
        int pb = pa + 1;
        unsigned ka[8], kb[8];
#pragma unroll
        for (int m = 0; m < 8; m++) {
            ka[m] = f2key(o_s[pa * OS_STRIDE + lid + 32 * m]);
            kb[m] = f2key(o_s[pb * OS_STRIDE + lid + 32 * m]);
        }
        unsigned ra = 0u, rb2 = 0u;
        for (int bit = 31; bit >= 0; bit--) {
            unsigned ca_ = ra  | (1u << bit);
            unsigned cb_ = rb2 | (1u << bit);
            unsigned na = 0, nb = 0;
#pragma unroll
            for (int m = 0; m < 8; m++) { na += (ka[m] >= ca_); nb += (kb[m] >= cb_); }
            na = __reduce_add_sync(0xffffffffu, na);
            nb = __reduce_add_sync(0xffffffffu, nb);
            if (na >= KTOP) ra  = ca_;
            if (nb >= KTOP) rb2 = cb_;
        }
        if (lid == 0) { tkey_s[pa] = ra; tkey_s[pb] = rb2; }
    }
    __syncthreads();

    // ---- band scan: elements within BAND of approx threshold
#pragma unroll 4
    for (int it = 0; it < 64; it++) {
        int i  = it * 512 + t;
        int co = i >> 7;
        int p  = i & 127;
        float vv = o_s[p * OS_STRIDE + co];
        float tv = key2f(tkey_s[p]);
        if (fabsf(vv - tv) < BAND) {
            int idx = atomicAdd(cnt_s, 1);
            if (idx < LISTCAP) list_s[idx] = (p << 8) | co;
        }
    }
    __syncthreads();

    // ---- exact fp32 recompute of band elements (one warp per element)
    {
        int cnt = min(cnt_s[0], LISTCAP);
        for (int e = wid; e < cnt; e += 16) {
            int pc = list_s[e];
            int p  = pc >> 8;
            int co = pc & 255;
            float acc = 0.f;
#pragma unroll
            for (int j = 0; j < 36; j++) {
                int k = lid + 32 * j;
                int ci = (k * 7282) >> 16;
                int r9 = k - 9 * ci;
                int kh = (r9 * 11) >> 5;
                int kw = r9 - 3 * kh;
                int y  = y0 + (p >> 6) + kh - 1;
                int xx = (p & 63) + kw - 1;
                float xv = ((unsigned)y < HH && (unsigned)xx < WW)
                           ? x[((b * CIN + ci) << 12) + (y << 6) + xx] : 0.f;
                acc += xv * w[co * 1152 + k];
            }
#pragma unroll
            for (int off = 16; off > 0; off >>= 1)
                acc += __shfl_xor_sync(0xffffffffu, acc, off);
            if (lid == 0) {
                float u = noise[((b * COUT + co) << 12) + (y0 << 6) + p];
                o_s[p * OS_STRIDE + co] = acc + wb_s[co] * (NOISE_SCALE * (2.f * u - 1.f));
            }
        }
    }
    __syncthreads();

    // ---- pass 2: exact 64th-largest on corrected values
    for (int ii = 0; ii < 4; ii++) {
        int pa = wid * 8 + ii * 2;
        int pb = pa + 1;
        unsigned ka[8], kb[8];
#pragma unroll
        for (int m = 0; m < 8; m++) {
            ka[m] = f2key(o_s[pa * OS_STRIDE + lid + 32 * m]);
            kb[m] = f2key(o_s[pb * OS_STRIDE + lid + 32 * m]);
        }
        unsigned ra = 0u, rb2 = 0u;
        for (int bit = 31; bit >= 0; bit--) {
            unsigned ca_ = ra  | (1u << bit);
            unsigned cb_ = rb2 | (1u << bit);
            unsigned na = 0, nb = 0;
#pragma unroll
            for (int m = 0; m < 8; m++) { na += (ka[m] >= ca_); nb += (kb[m] >= cb_); }
            na = __reduce_add_sync(0xffffffffu, na);
            nb = __reduce_add_sync(0xffffffffu, nb);
            if (na >= KTOP) ra  = ca_;
            if (nb >= KTOP) rb2 = cb_;
        }
        if (lid == 0) { tkey_s[pa] = ra; tkey_s[pb] = rb2; }
    }
    __syncthreads();

    // ---- threshold (>= keeps ties) + relu_bias + relu, coalesced store
#pragma unroll 4
    for (int it = 0; it < 64; it++) {
        int i  = it * 512 + t;
        int co = i >> 7;
        int p  = i & 127;
        float vv = o_s[p * OS_STRIDE + co];
        float r = (f2key(vv) >= tkey_s[p]) ? vv : 0.f;
        r = fmaxf(r + rb_s[co], 0.f);
        out[((b * COUT + co) << 12) + (y0 << 6) + p] = r;
    }
}

extern "C" void kernel_launch(void* const* d_in, const int* in_sizes, int n_in,
                              void* d_out, int out_size) {
    const float* x  = (const float*)d_in[0];
    const float* w  = (const float*)d_in[1];
    const float* rb = (const float*)d_in[2];
    const float* nu = (const float*)d_in[3];
    float* out = (float*)d_out;

    cudaFuncSetAttribute(conv_mma_kernel,
                         cudaFuncAttributeMaxDynamicSharedMemorySize, SMEM_BYTES);

    prep_whalf<<<256, 128>>>(w);
    prep_bias<<<256, 128>>>(w);
    conv_mma_kernel<<<dim3(32, 32), 512, SMEM_BYTES>>>(x, w, rb, nu, out);
}

// round 11
// speedup vs baseline: 1.9757x; 1.0888x over previous
#include <cuda_runtime.h>
#include <cuda_fp16.h>
#include <cstdint>

#define CIN 128
#define COUT 256
#define HH 64
#define WW 64
#define KTOP 64
#define NOISE_SCALE (8.0f/255.0f)

#define NSTG 36              // K = 1152 = 36 chunks of 32 (2 x k16 halves), tap-major
#define BAND 4.5e-3f
#define LISTCAP 512

// ---- smem layout ----
#define AS_B 0               // A: [stage2][ks2][128 pix][32B] = 16384 B
#define BS_B 16384           // B: [stage2][ks2][256 ch ][32B] = 32768 B (end 49152)
#define OS_STRIDE 258
#define RB_F 33024
#define WB_F (RB_F+256)
#define TK_F (WB_F+256)
#define CNT_F (TK_F+128)
#define LIST_F (CNT_F+4)
#define SMEM_F (LIST_F+LISTCAP)
#define SMEM_BYTES (SMEM_F*4)

// prepped weights fp16, tap-major K: [stage][ks][co][q] as uint2
// word q: .x = klocal {2q,2q+1}, .y = {2q+8,2q+9}; klocal = ci within k16
__device__ uint2 g_wh[NSTG * 2 * COUT * 4];
__device__ float g_wbias[COUT];

__device__ __forceinline__ uint32_t smem_to_u32(const void* p) {
    uint32_t a;
    asm("{ .reg .u64 t; cvta.to.shared.u64 t, %1; cvt.u32.u64 %0, t; }" : "=r"(a) : "l"(p));
    return a;
}
__device__ __forceinline__ unsigned f2key(float v) {
    unsigned u = __float_as_uint(v);
    return (u & 0x80000000u) ? ~u : (u | 0x80000000u);
}
__device__ __forceinline__ float key2f(unsigned k) {
    unsigned u = (k & 0x80000000u) ? (k & 0x7fffffffu) : ~k;
    return __uint_as_float(u);
}
__device__ __forceinline__ unsigned h2(float lo, float hi) {
    __half2 p = __floats2half2_rn(lo, hi);
    return *(unsigned*)&p;
}

#define MMA_FP16(dv, a0, a1, a2, a3, b0, b1) \
    asm volatile("mma.sync.aligned.m16n8k16.row.col.f32.f16.f16.f32 " \
        "{%0,%1,%2,%3}, {%4,%5,%6,%7}, {%8,%9}, {%0,%1,%2,%3};" \
        : "+f"((dv)[0]), "+f"((dv)[1]), "+f"((dv)[2]), "+f"((dv)[3]) \
        : "r"(a0), "r"(a1), "r"(a2), "r"(a3), "r"(b0), "r"(b1))

#define CP_ASYNC16(dst_u32, src_ptr) \
    asm volatile("cp.async.ca.shared.global [%0], [%1], 16;" :: "r"(dst_u32), "l"(src_ptr))
#define CP_COMMIT()  asm volatile("cp.async.commit_group;")
#define CP_WAIT0()   asm volatile("cp.async.wait_group 0;" ::: "memory")

__device__ __forceinline__ int a_addr(int stg, int ks, int p, int q) {
    return AS_B + ((stg * 2 + ks) * 128 + p) * 32 + q * 8;
}
__device__ __forceinline__ int b_addr(int stg, int ks, int n, int q) {
    return BS_B + ((stg * 2 + ks) * 256 + n) * 32 + q * 8;
}

// ---------------- prep kernels ----------------
// tap-major: k' = tap*128 + ci ; stage = k'>>5, ks = (k'>>4)&1, klocal = k'&15
__global__ void prep_whalf(const float* __restrict__ w) {
    int co = blockIdx.x;
    unsigned short* dst = (unsigned short*)g_wh;
    for (int kp = threadIdx.x; kp < 1152; kp += 128) {
        int tap = kp >> 7;
        int ci  = kp & 127;
        float v = w[co * 1152 + ci * 9 + tap];
        int cstg = kp >> 5;
        int ks = (kp >> 4) & 1;
        int j = kp & 15;
        int q = (j & 7) >> 1, half = j >> 3, slot = j & 1;
        int idx = ((((cstg * 2 + ks) * COUT + co) * 4 + q) * 4) + half * 2 + slot;
        dst[idx] = __half_as_ushort(__float2half(v));
    }
}
__global__ void prep_bias(const float* __restrict__ w) {
    __shared__ float red[128];
    int co = blockIdx.x;
    float s = 0.f;
    for (int j = threadIdx.x; j < 1152; j += 128) s += fabsf(w[co * 1152 + j]);
    red[threadIdx.x] = s;
    __syncthreads();
    for (int off = 64; off > 0; off >>= 1) {
        if (threadIdx.x < off) red[threadIdx.x] += red[threadIdx.x + off];
        __syncthreads();
    }
    if (threadIdx.x == 0) g_wbias[co] = red[0];
}

// ---------------- main fused kernel ----------------
// CTA: 128 pixels (2 rows x 64) x 256 couts, 512 threads (16 warps).
// warp (wm = wid&3, wn = wid>>2): 2 m-tiles x 8 n-tiles of m16n8k16 fp16, 1 pass.
__global__ void __launch_bounds__(512, 1)
conv_mma_kernel(const float* __restrict__ x, const float* __restrict__ w,
                const float* __restrict__ rbias,
                const float* __restrict__ noise, float* __restrict__ out) {
    extern __shared__ float smem[];
    char* smc = (char*)smem;
    const uint32_t smem_base = smem_to_u32(smem);
    const int t   = threadIdx.x;
    const int wid = t >> 5;
    const int lid = t & 31;
    const int g   = lid >> 2;
    const int tig = lid & 3;
    const int b   = blockIdx.y;
    const int y0  = blockIdx.x * 2;

    const int wm = wid & 3;
    const int wn = wid >> 2;

    float* rb_s = smem + RB_F;
    float* wb_s = smem + WB_F;
    unsigned* tkey_s = (unsigned*)(smem + TK_F);
    int* cnt_s = (int*)(smem + CNT_F);
    int* list_s = (int*)(smem + LIST_F);
    if (t < 256) { rb_s[t] = rbias[t]; wb_s[t] = g_wbias[t]; }
    if (t == 0) cnt_s[0] = 0;

    float d[2][8][4];
#pragma unroll
    for (int i = 0; i < 2; i++)
#pragma unroll
        for (int j = 0; j < 8; j++)
#pragma unroll
            for (int q = 0; q < 4; q++) d[i][j][q] = 0.f;

    const int ap  = t >> 2;      // A-build pixel 0..127
    const int aq  = t & 3;       // A-build q group
    const int apy = ap >> 6;
    const int apx = ap & 63;
    const float* xb = x + ((size_t)b << 19);   // b*CIN*4096

    // ci offsets for the 8 A values: jj -> ks = jj>>2, cilocal = 2aq + (jj&1) + ((jj>>1)&1)*8
    // A-build for one stage, tap fixed:
    auto a_build_load = [&](int c, float v[8]) {
        int tap = c >> 2;
        int kh = (tap * 11) >> 5;
        int kw = tap - 3 * kh;
        int y  = y0 + apy + kh - 1;
        int xx = apx + kw - 1;
        bool ok = ((unsigned)y < HH) && ((unsigned)xx < WW);
        const float* xp = xb + ((c & 3) << 17) + (y << 6) + xx;  // ci0*4096 = (c&3)*32*4096
#pragma unroll
        for (int jj = 0; jj < 8; jj++) {
            int ci_off = ((jj >> 2) << 4) + 2 * aq + (jj & 1) + (((jj >> 1) & 1) << 3);
            v[jj] = ok ? __ldg(xp + (ci_off << 12)) : 0.f;
        }
    };

    // ---- prologue: stage 0
    {
        const char* bsrc = (const char*)g_wh;
#pragma unroll
        for (int it = 0; it < 2; it++) {
            int i = it * 512 + t;
            CP_ASYNC16(smem_base + (uint32_t)(BS_B + i * 16), bsrc + i * 16);
        }
        CP_COMMIT();
        float v[8];
        a_build_load(0, v);
        *(uint2*)(smc + a_addr(0, 0, ap, aq)) = make_uint2(h2(v[0], v[1]), h2(v[2], v[3]));
        *(uint2*)(smc + a_addr(0, 1, ap, aq)) = make_uint2(h2(v[4], v[5]), h2(v[6], v[7]));
        CP_WAIT0();
        __syncthreads();
    }

    for (int c = 0; c < NSTG; c++) {
        const int cur = c & 1, nxt = cur ^ 1;
        const bool pf = (c < NSTG - 1);
        if (pf) {
            const char* bsrc = (const char*)(g_wh + (size_t)(c + 1) * 2 * COUT * 4);
#pragma unroll
            for (int it = 0; it < 2; it++) {
                int i = it * 512 + t;
                CP_ASYNC16(smem_base + (uint32_t)(BS_B + nxt * 16384 + i * 16), bsrc + i * 16);
            }
            CP_COMMIT();
        }
        float v[8];
        if (pf) a_build_load(c + 1, v);
        // ---- compute: 2 k16-halves, 2 m-tiles x 8 n-tiles
#pragma unroll
        for (int ks = 0; ks < 2; ks++) {
            uint2 af[2][2];
#pragma unroll
            for (int mt = 0; mt < 2; mt++) {
                int m0 = wm * 32 + mt * 16 + g;
                af[mt][0] = *(const uint2*)(smc + a_addr(cur, ks, m0,     tig));
                af[mt][1] = *(const uint2*)(smc + a_addr(cur, ks, m0 + 8, tig));
            }
#pragma unroll
            for (int nt = 0; nt < 8; nt++) {
                int n = wn * 64 + nt * 8 + g;
                uint2 bf_ = *(const uint2*)(smc + b_addr(cur, ks, n, tig));
#pragma unroll
                for (int mt = 0; mt < 2; mt++) {
                    MMA_FP16(d[mt][nt], af[mt][0].x, af[mt][1].x, af[mt][0].y, af[mt][1].y,
                             bf_.x, bf_.y);
                }
            }
        }
        if (pf) {
            *(uint2*)(smc + a_addr(nxt, 0, ap, aq)) = make_uint2(h2(v[0], v[1]), h2(v[2], v[3]));
            *(uint2*)(smc + a_addr(nxt, 1, ap, aq)) = make_uint2(h2(v[4], v[5]), h2(v[6], v[7]));
            CP_WAIT0();
        }
        __syncthreads();
    }

    // ---- epilogue: spill accums to o_s[p*258 + co]
    float* o_s = smem;
#pragma unroll
    for (int mt = 0; mt < 2; mt++) {
#pragma unroll
        for (int nt = 0; nt < 8; nt++) {
            int p  = wm * 32 + mt * 16 + g;
            int co = wn * 64 + nt * 8 + 2 * tig;
            *(float2*)&o_s[p * OS_STRIDE + co]       = make_float2(d[mt][nt][0], d[mt][nt][1]);
            *(float2*)&o_s[(p + 8) * OS_STRIDE + co] = make_float2(d[mt][nt][2], d[mt][nt][3]);
        }
    }
    __syncthreads();

    // ---- noise inject
#pragma unroll 4
    for (int it = 0; it < 64; it++) {
        int i  = it * 512 + t;
        int co = i >> 7;
        int p  = i & 127;
        float u = noise[((b * COUT + co) << 12) + (y0 << 6) + p];
        o_s[p * OS_STRIDE + co] += wb_s[co] * (NOISE_SCALE * (2.f * u - 1.f));
    }
    __syncthreads();

    // ---- pass 1: approx kth (bits 31..9, packed counts) + fused band collect
    for (int ii = 0; ii < 4; ii++) {
        int pa = wid * 8 + ii * 2;
        int pb = pa + 1;
        unsigned ka[8], kb[8];
#pragma unroll
        for (int m = 0; m < 8; m++) {
            ka[m] = f2key(o_s[pa * OS_STRIDE + lid + 32 * m]);
            kb[m] = f2key(o_s[pb * OS_STRIDE + lid + 32 * m]);
        }
        unsigned ra = 0u, rb2 = 0u;
        for (int bit = 31; bit >= 9; bit--) {
            unsigned ca_ = ra  | (1u << bit);
            unsigned cb_ = rb2 | (1u << bit);
            unsigned cnt = 0;
#pragma unroll
            for (int m = 0; m < 8; m++)
                cnt += (ka[m] >= ca_) + ((kb[m] >= cb_) << 16);
            cnt = __reduce_add_sync(0xffffffffu, cnt);
            if ((cnt & 0xffffu) >= KTOP) ra  = ca_;
            if ((cnt >> 16)     >= KTOP) rb2 = cb_;
        }
        if (lid == 0) { tkey_s[pa] = ra; tkey_s[pb] = rb2; }
        // fused band collect (keys in regs)
        float tva = key2f(ra), tvb = key2f(rb2);
        unsigned kloA = f2key(tva - BAND), khiA = f2key(tva + BAND);
        unsigned kloB = f2key(tvb - BAND), khiB = f2key(tvb + BAND);
#pragma unroll
        for (int m = 0; m < 8; m++) {
            if (ka[m] >= kloA && ka[m] <= khiA) {
                int idx = atomicAdd(cnt_s, 1);
                if (idx < LISTCAP) list_s[idx] = (pa << 8) | (lid + 32 * m);
            }
            if (kb[m] >= kloB && kb[m] <= khiB) {
                int idx = atomicAdd(cnt_s, 1);
                if (idx < LISTCAP) list_s[idx] = (pb << 8) | (lid + 32 * m);
            }
        }
    }
    __syncthreads();

    // ---- exact fp32 recompute of band elements (one warp per element)
    {
        int cnt = min(cnt_s[0], LISTCAP);
        for (int e = wid; e < cnt; e += 16) {
            int pc = list_s[e];
            int p  = pc >> 8;
            int co = pc & 255;
            float acc = 0.f;
#pragma unroll
            for (int j = 0; j < 36; j++) {
                int k = lid + 32 * j;
                int ci = (k * 7282) >> 16;
                int r9 = k - 9 * ci;
                int kh = (r9 * 11) >> 5;
                int kw = r9 - 3 * kh;
                int y  = y0 + (p >> 6) + kh - 1;
                int xx = (p & 63) + kw - 1;
                float xv = ((unsigned)y < HH && (unsigned)xx < WW)
                           ? x[((b * CIN + ci) << 12) + (y << 6) + xx] : 0.f;
                acc += xv * w[co * 1152 + k];
            }
#pragma unroll
            for (int off = 16; off > 0; off >>= 1)
                acc += __shfl_xor_sync(0xffffffffu, acc, off);
            if (lid == 0) {
                float u = noise[((b * COUT + co) << 12) + (y0 << 6) + p];
                o_s[p * OS_STRIDE + co] = acc + wb_s[co] * (NOISE_SCALE * (2.f * u - 1.f));
            }
        }
    }
    __syncthreads();

    // ---- pass 2: exact kth on corrected values, prefix-narrowed to [T +/- 2*BAND]
    for (int ii = 0; ii < 4; ii++) {
        int pa = wid * 8 + ii * 2;
        int pb = pa + 1;
        float tva = key2f(tkey_s[pa]);
        float tvb = key2f(tkey_s[pb]);
        unsigned kloA = f2key(tva - 2.f * BAND), khiA = f2key(tva + 2.f * BAND);
        unsigned kloB = f2key(tvb - 2.f * BAND), khiB = f2key(tvb + 2.f * BAND);
        int hbA = 31 - __clz((kloA ^ khiA) | 1);
        int hbB = 31 - __clz((kloB ^ khiB) | 1);
        int hb  = hbA > hbB ? hbA : hbB;
        unsigned maskhi = (hb >= 31) ? 0u : ~((2u << hb) - 1u);
        unsigned ra  = kloA & maskhi;
        unsigned rb2 = kloB & maskhi;
        unsigned ka[8], kb[8];
#pragma unroll
        for (int m = 0; m < 8; m++) {
            ka[m] = f2key(o_s[pa * OS_STRIDE + lid + 32 * m]);
            kb[m] = f2key(o_s[pb * OS_STRIDE + lid + 32 * m]);
        }
        for (int bit = hb; bit >= 0; bit--) {
            unsigned ca_ = ra  | (1u << bit);
            unsigned cb_ = rb2 | (1u << bit);
            unsigned cnt = 0;
#pragma unroll
            for (int m = 0; m < 8; m++)
                cnt += (ka[m] >= ca_) + ((kb[m] >= cb_) << 16);
            cnt = __reduce_add_sync(0xffffffffu, cnt);
            if ((cnt & 0xffffu) >= KTOP) ra  = ca_;
            if ((cnt >> 16)     >= KTOP) rb2 = cb_;
        }
        if (lid == 0) { tkey_s[pa] = ra; tkey_s[pb] = rb2; }
    }
    __syncthreads();

    // ---- threshold (>= keeps ties) + relu_bias + relu, coalesced store
#pragma unroll 4
    for (int it = 0; it < 64; it++) {
        int i  = it * 512 + t;
        int co = i >> 7;
        int p  = i & 127;
        float vv = o_s[p * OS_STRIDE + co];
        float r = (f2key(vv) >= tkey_s[p]) ? vv : 0.f;
        r = fmaxf(r + rb_s[co], 0.f);
        out[((b * COUT + co) << 12) + (y0 << 6) + p] = r;
    }
}

extern "C" void kernel_launch(void* const* d_in, const int* in_sizes, int n_in,
                              void* d_out, int out_size) {
    const float* x  = (const float*)d_in[0];
    const float* w  = (const float*)d_in[1];
    const float* rb = (const float*)d_in[2];
    const float* nu = (const float*)d_in[3];
    float* out = (float*)d_out;

    cudaFuncSetAttribute(conv_mma_kernel,
                         cudaFuncAttributeMaxDynamicSharedMemorySize, SMEM_BYTES);

    prep_whalf<<<256, 128>>>(w);
    prep_bias<<<256, 128>>>(w);
    conv_mma_kernel<<<dim3(32, 32), 512, SMEM_BYTES>>>(x, w, rb, nu, out);
}

// round 13
// speedup vs baseline: 2.0264x; 1.0257x over previous
#include <cuda_runtime.h>
#include <cuda_fp16.h>
#include <cstdint>

#define CIN 128
#define COUT 256
#define HH 64
#define WW 64
#define KTOP 64
#define NOISE_SCALE (8.0f/255.0f)

#define NSTG 18              // K = 1152 = 18 chunks of 64 (4 x k16 halves), tap-major
#define BAND 4.5e-3f
#define LISTCAP 512

// ---- smem layout ----
#define AS_B 0               // A: [stage2][ks4][128 pix][32B] = 32768 B
#define BS_B 32768           // B: [stage2][ks4][256 ch ][32B] = 65536 B (end 98304)
#define OS_STRIDE 258
#define RB_F 33024
#define WB_F (RB_F+256)
#define TK_F (WB_F+256)
#define CNT_F (TK_F+128)
#define LIST_F (CNT_F+4)
#define SMEM_F (LIST_F+LISTCAP)
#define SMEM_BYTES (SMEM_F*4)

// prepped weights fp16, tap-major K: [stage][ks4][co][q] as uint2
// word q: .x = klocal {2q,2q+1}, .y = {2q+8,2q+9}
__device__ uint2 g_wh[NSTG * 4 * COUT * 4];
__device__ float g_wbias[COUT];

__device__ __forceinline__ uint32_t smem_to_u32(const void* p) {
    uint32_t a;
    asm("{ .reg .u64 t; cvta.to.shared.u64 t, %1; cvt.u32.u64 %0, t; }" : "=r"(a) : "l"(p));
    return a;
}
__device__ __forceinline__ unsigned f2key(float v) {
    unsigned u = __float_as_uint(v);
    return (u & 0x80000000u) ? ~u : (u | 0x80000000u);
}
__device__ __forceinline__ float key2f(unsigned k) {
    unsigned u = (k & 0x80000000u) ? (k & 0x7fffffffu) : ~k;
    return __uint_as_float(u);
}
__device__ __forceinline__ unsigned h2(float lo, float hi) {
    __half2 p = __floats2half2_rn(lo, hi);
    return *(unsigned*)&p;
}

#define MMA_FP16(dv, a0, a1, a2, a3, b0, b1) \
    asm volatile("mma.sync.aligned.m16n8k16.row.col.f32.f16.f16.f32 " \
        "{%0,%1,%2,%3}, {%4,%5,%6,%7}, {%8,%9}, {%0,%1,%2,%3};" \
        : "+f"((dv)[0]), "+f"((dv)[1]), "+f"((dv)[2]), "+f"((dv)[3]) \
        : "r"(a0), "r"(a1), "r"(a2), "r"(a3), "r"(b0), "r"(b1))

#define CP_ASYNC16(dst_u32, src_ptr) \
    asm volatile("cp.async.ca.shared.global [%0], [%1], 16;" :: "r"(dst_u32), "l"(src_ptr))
#define CP_COMMIT()  asm volatile("cp.async.commit_group;")
#define CP_WAIT0()   asm volatile("cp.async.wait_group 0;" ::: "memory")

__device__ __forceinline__ int a_addr(int stg, int ks, int p, int q) {
    return AS_B + ((stg * 4 + ks) * 128 + p) * 32 + q * 8;
}
__device__ __forceinline__ int b_addr(int stg, int ks, int n, int q) {
    return BS_B + ((stg * 4 + ks) * 256 + n) * 32 + q * 8;
}

// ---------------- merged prep kernel ----------------
// tap-major: k' = tap*128 + ci ; stage = k'>>6, ks = (k'>>4)&3, klocal = k'&15
__global__ void prep_all(const float* __restrict__ w) {
    __shared__ float red[128];
    int co = blockIdx.x;
    unsigned short* dst = (unsigned short*)g_wh;
    float s = 0.f;
    for (int kp = threadIdx.x; kp < 1152; kp += 128) {
        int tap = kp >> 7;
        int ci  = kp & 127;
        float v = w[co * 1152 + ci * 9 + tap];
        s += fabsf(v);
        int cstg = kp >> 6;
        int ks = (kp >> 4) & 3;
        int j = kp & 15;
        int q = (j & 7) >> 1, half = j >> 3, slot = j & 1;
        int idx = ((((cstg * 4 + ks) * COUT + co) * 4 + q) * 4) + half * 2 + slot;
        dst[idx] = __half_as_ushort(__float2half(v));
    }
    red[threadIdx.x] = s;
    __syncthreads();
    for (int off = 64; off > 0; off >>= 1) {
        if (threadIdx.x < off) red[threadIdx.x] += red[threadIdx.x + off];
        __syncthreads();
    }
    if (threadIdx.x == 0) g_wbias[co] = red[0];
}

// ---------------- main fused kernel ----------------
// CTA: 128 pixels (2 rows x 64) x 256 couts, 512 threads (16 warps).
// warp (wm = wid&3, wn = wid>>2): 2 m-tiles x 8 n-tiles of m16n8k16 fp16,
// 4 k16-halves per 64-k stage.
__global__ void __launch_bounds__(512, 1)
conv_mma_kernel(const float* __restrict__ x, const float* __restrict__ w,
                const float* __restrict__ rbias,
                const float* __restrict__ noise, float* __restrict__ out) {
    extern __shared__ float smem[];
    char* smc = (char*)smem;
    const uint32_t smem_base = smem_to_u32(smem);
    const int t   = threadIdx.x;
    const int wid = t >> 5;
    const int lid = t & 31;
    const int g   = lid >> 2;
    const int tig = lid & 3;
    const int b   = blockIdx.y;
    const int y0  = blockIdx.x * 2;

    const int wm = wid & 3;
    const int wn = wid >> 2;

    float* rb_s = smem + RB_F;
    float* wb_s = smem + WB_F;
    unsigned* tkey_s = (unsigned*)(smem + TK_F);
    int* cnt_s = (int*)(smem + CNT_F);
    int* list_s = (int*)(smem + LIST_F);
    if (t < 256) { rb_s[t] = rbias[t]; wb_s[t] = g_wbias[t]; }
    if (t == 0) cnt_s[0] = 0;

    float d[2][8][4];
#pragma unroll
    for (int i = 0; i < 2; i++)
#pragma unroll
        for (int j = 0; j < 8; j++)
#pragma unroll
            for (int q = 0; q < 4; q++) d[i][j][q] = 0.f;

    const int ap  = t >> 2;      // A-build pixel 0..127
    const int aq  = t & 3;       // A-build q group
    const int apy = ap >> 6;
    const int apx = ap & 63;
    const float* xb = x + ((size_t)b << 19);   // b*CIN*4096

    // one 64-k stage = one tap (c>>1), ci range (c&1)*64 .. +63
    auto a_build_load = [&](int c, float v[16]) {
        int tap = c >> 1;
        int kh = (tap * 11) >> 5;
        int kw = tap - 3 * kh;
        int y  = y0 + apy + kh - 1;
        int xx = apx + kw - 1;
        bool ok = ((unsigned)y < HH) && ((unsigned)xx < WW);
        const float* xp = xb + (((c & 1) * 64) << 12) + (y << 6) + xx;
#pragma unroll
        for (int jj = 0; jj < 16; jj++) {
            int ks = jj >> 2, sub = jj & 3;
            int ci_off = (ks << 4) + 2 * aq + (sub & 1) + (((sub >> 1) & 1) << 3);
            v[jj] = ok ? __ldg(xp + (ci_off << 12)) : 0.f;
        }
    };
    auto a_store = [&](int stg, int c, float v[16]) {
        (void)c;
#pragma unroll
        for (int ks = 0; ks < 4; ks++) {
            *(uint2*)(smc + a_addr(stg, ks, ap, aq)) =
                make_uint2(h2(v[4*ks+0], v[4*ks+1]), h2(v[4*ks+2], v[4*ks+3]));
        }
    };

    // ---- prologue: stage 0
    {
        const char* bsrc = (const char*)g_wh;
#pragma unroll
        for (int it = 0; it < 4; it++) {
            int i = it * 512 + t;                 // 16B unit 0..2047
            CP_ASYNC16(smem_base + (uint32_t)(BS_B + i * 16), bsrc + i * 16);
        }
        CP_COMMIT();
        float v[16];
        a_build_load(0, v);
        a_store(0, 0, v);
        CP_WAIT0();
        __syncthreads();
    }

    for (int c = 0; c < NSTG; c++) {
        const int cur = c & 1, nxt = cur ^ 1;
        const bool pf = (c < NSTG - 1);
        if (pf) {
            const char* bsrc = (const char*)(g_wh + (size_t)(c + 1) * 4 * COUT * 4);
#pragma unroll
            for (int it = 0; it < 4; it++) {
                int i = it * 512 + t;
                CP_ASYNC16(smem_base + (uint32_t)(BS_B + nxt * 32768 + i * 16), bsrc + i * 16);
            }
            CP_COMMIT();
        }
        float v[16];
        if (pf) a_build_load(c + 1, v);
        // ---- compute: 4 k16-halves, 2 m-tiles x 8 n-tiles
#pragma unroll
        for (int ks = 0; ks < 4; ks++) {
            uint2 af[2][2];
#pragma unroll
            for (int mt = 0; mt < 2; mt++) {
                int m0 = wm * 32 + mt * 16 + g;
                af[mt][0] = *(const uint2*)(smc + a_addr(cur, ks, m0,     tig));
                af[mt][1] = *(const uint2*)(smc + a_addr(cur, ks, m0 + 8, tig));
            }
#pragma unroll
            for (int nt = 0; nt < 8; nt++) {
                int n = wn * 64 + nt * 8 + g;
                uint2 bf_ = *(const uint2*)(smc + b_addr(cur, ks, n, tig));
#pragma unroll
                for (int mt = 0; mt < 2; mt++) {
                    MMA_FP16(d[mt][nt], af[mt][0].x, af[mt][1].x, af[mt][0].y, af[mt][1].y,
                             bf_.x, bf_.y);
                }
            }
        }
        if (pf) {
            a_store(nxt, c + 1, v);
            CP_WAIT0();
        }
        __syncthreads();
    }

    // ---- epilogue: spill accums to o_s[p*258 + co]
    float* o_s = smem;
#pragma unroll
    for (int mt = 0; mt < 2; mt++) {
#pragma unroll
        for (int nt = 0; nt < 8; nt++) {
            int p  = wm * 32 + mt * 16 + g;
            int co = wn * 64 + nt * 8 + 2 * tig;
            *(float2*)&o_s[p * OS_STRIDE + co]       = make_float2(d[mt][nt][0], d[mt][nt][1]);
            *(float2*)&o_s[(p + 8) * OS_STRIDE + co] = make_float2(d[mt][nt][2], d[mt][nt][3]);
        }
    }
    __syncthreads();

    // ---- noise inject
#pragma unroll 4
    for (int it = 0; it < 64; it++) {
        int i  = it * 512 + t;
        int co = i >> 7;
        int p  = i & 127;
        float u = noise[((b * COUT + co) << 12) + (y0 << 6) + p];
        o_s[p * OS_STRIDE + co] += wb_s[co] * (NOISE_SCALE * (2.f * u - 1.f));
    }
    __syncthreads();

    // ---- pass 1: approx kth (bits 31..9, packed counts) + fused band collect
    for (int ii = 0; ii < 4; ii++) {
        int pa = wid * 8 + ii * 2;
        int pb = pa + 1;
        unsigned ka[8], kb[8];
#pragma unroll
        for (int m = 0; m < 8; m++) {
            ka[m] = f2key(o_s[pa * OS_STRIDE + lid + 32 * m]);
            kb[m] = f2key(o_s[pb * OS_STRIDE + lid + 32 * m]);
        }
        unsigned ra = 0u, rb2 = 0u;
        for (int bit = 31; bit >= 9; bit--) {
            unsigned ca_ = ra  | (1u << bit);
            unsigned cb_ = rb2 | (1u << bit);
            unsigned cnt = 0;
#pragma unroll
            for (int m = 0; m < 8; m++)
                cnt += (ka[m] >= ca_) + ((kb[m] >= cb_) << 16);
            cnt = __reduce_add_sync(0xffffffffu, cnt);
            if ((cnt & 0xffffu) >= KTOP) ra  = ca_;
            if ((cnt >> 16)     >= KTOP) rb2 = cb_;
        }
        if (lid == 0) { tkey_s[pa] = ra; tkey_s[pb] = rb2; }
        float tva = key2f(ra), tvb = key2f(rb2);
        unsigned kloA = f2key(tva - BAND), khiA = f2key(tva + BAND);
        unsigned kloB = f2key(tvb - BAND), khiB = f2key(tvb + BAND);
#pragma unroll
        for (int m = 0; m < 8; m++) {
            if (ka[m] >= kloA && ka[m] <= khiA) {
                int idx = atomicAdd(cnt_s, 1);
                if (idx < LISTCAP) list_s[idx] = (pa << 8) | (lid + 32 * m);
            }
            if (kb[m] >= kloB && kb[m] <= khiB) {
                int idx = atomicAdd(cnt_s, 1);
                if (idx < LISTCAP) list_s[idx] = (pb << 8) | (lid + 32 * m);
            }
        }
    }
    __syncthreads();

    // ---- exact fp32 recompute of band elements (one warp per element)
    {
        int cnt = min(cnt_s[0], LISTCAP);
        for (int e = wid; e < cnt; e += 16) {
            int pc = list_s[e];
            int p  = pc >> 8;
            int co = pc & 255;
            float acc = 0.f;
#pragma unroll
            for (int j = 0; j < 36; j++) {
                int k = lid + 32 * j;
                int ci = (k * 7282) >> 16;
                int r9 = k - 9 * ci;
                int kh = (r9 * 11) >> 5;
                int kw = r9 - 3 * kh;
                int y  = y0 + (p >> 6) + kh - 1;
                int xx = (p & 63) + kw - 1;
                float xv = ((unsigned)y < HH && (unsigned)xx < WW)
                           ? x[((b * CIN + ci) << 12) + (y << 6) + xx] : 0.f;
                acc += xv * w[co * 1152 + k];
            }
#pragma unroll
            for (int off = 16; off > 0; off >>= 1)
                acc += __shfl_xor_sync(0xffffffffu, acc, off);
            if (lid == 0) {
                float u = noise[((b * COUT + co) << 12) + (y0 << 6) + p];
                o_s[p * OS_STRIDE + co] = acc + wb_s[co] * (NOISE_SCALE * (2.f * u - 1.f));
            }
        }
    }
    __syncthreads();

    // ---- pass 2: exact kth on corrected values, prefix-narrowed to [T +/- 2*BAND]
    for (int ii = 0; ii < 4; ii++) {
        int pa = wid * 8 + ii * 2;
        int pb = pa + 1;
        float tva = key2f(tkey_s[pa]);
        float tvb = key2f(tkey_s[pb]);
        unsigned kloA = f2key(tva - 2.f * BAND), khiA = f2key(tva + 2.f * BAND);
        unsigned kloB = f2key(tvb - 2.f * BAND), khiB = f2key(tvb + 2.f * BAND);
        int hbA = 31 - __clz((kloA ^ khiA) | 1);
        int hbB = 31 - __clz((kloB ^ khiB) | 1);
        int hb  = hbA > hbB ? hbA : hbB;
        unsigned maskhi = (hb >= 31) ? 0u : ~((2u << hb) - 1u);
        unsigned ra  = kloA & maskhi;
        unsigned rb2 = kloB & maskhi;
        unsigned ka[8], kb[8];
#pragma unroll
        for (int m = 0; m < 8; m++) {
            ka[m] = f2key(o_s[pa * OS_STRIDE + lid + 32 * m]);
            kb[m] = f2key(o_s[pb * OS_STRIDE + lid + 32 * m]);
        }
        for (int bit = hb; bit >= 0; bit--) {
            unsigned ca_ = ra  | (1u << bit);
            unsigned cb_ = rb2 | (1u << bit);
            unsigned cnt = 0;
#pragma unroll
            for (int m = 0; m < 8; m++)
                cnt += (ka[m] >= ca_) + ((kb[m] >= cb_) << 16);
            cnt = __reduce_add_sync(0xffffffffu, cnt);
            if ((cnt & 0xffffu) >= KTOP) ra  = ca_;
            if ((cnt >> 16)     >= KTOP) rb2 = cb_;
        }
        if (lid == 0) { tkey_s[pa] = ra; tkey_s[pb] = rb2; }
    }
    __syncthreads();

    // ---- threshold (>= keeps ties) + relu_bias + relu, coalesced store
#pragma unroll 4
    for (int it = 0; it < 64; it++) {
        int i  = it * 512 + t;
        int co = i >> 7;
        int p  = i & 127;
        float vv = o_s[p * OS_STRIDE + co];
        float r = (f2key(vv) >= tkey_s[p]) ? vv : 0.f;
        r = fmaxf(r + rb_s[co], 0.f);
        out[((b * COUT + co) << 12) + (y0 << 6) + p] = r;
    }
}

extern "C" void kernel_launch(void* const* d_in, const int* in_sizes, int n_in,
                              void* d_out, int out_size) {
    const float* x  = (const float*)d_in[0];
    const float* w  = (const float*)d_in[1];
    const float* rb = (const float*)d_in[2];
    const float* nu = (const float*)d_in[3];
    float* out = (float*)d_out;

    cudaFuncSetAttribute(conv_mma_kernel,
                         cudaFuncAttributeMaxDynamicSharedMemorySize, SMEM_BYTES);

    prep_all<<<256, 128>>>(w);
    conv_mma_kernel<<<dim3(32, 32), 512, SMEM_BYTES>>>(x, w, rb, nu, out);
}

// round 15
// speedup vs baseline: 2.9216x; 1.4417x over previous
#include <cuda_runtime.h>
#include <cuda_fp16.h>
#include <cstdint>

#define CIN 128
#define COUT 256
#define HH 64
#define WW 64
#define KTOP 64
#define NOISE_SCALE (8.0f/255.0f)

#define NSTG 18              // K = 1152 = 18 chunks of 64 (4 x k16 halves), tap-major
#define BAND 4.5e-3f
#define LISTCAP 512

// ---- smem layout (bytes / floats) ----
// A: [stage2][ks4][64 pix][32B] = 16384 B at 0
// B: [stage2][ks4][256 co][32B] = 65536 B at 16384  (end 81920)
// o_s overlay: 64*257 floats = 65792 B at 0 (odd stride -> conflict-free epilogue)
#define AS_B 0
#define BS_B 16384
#define OS_STRIDE 257
#define RB_F 20480           // = 81920/4, beyond mainloop region
#define WB_F (RB_F+256)
#define TK_F (WB_F+256)
#define CNT_F (TK_F+64)
#define LIST_F (CNT_F+4)
#define SMEM_F (LIST_F+LISTCAP)
#define SMEM_BYTES (SMEM_F*4)   // ~85 KB -> 2 CTAs/SM

// prepped weights fp16, tap-major K: [stage][ks4][co][q] as uint2
// word q: .x = klocal {2q,2q+1}, .y = {2q+8,2q+9}
__device__ uint2 g_wh[NSTG * 4 * COUT * 4];
__device__ float g_wbias[COUT];

__device__ __forceinline__ uint32_t smem_to_u32(const void* p) {
    uint32_t a;
    asm("{ .reg .u64 t; cvta.to.shared.u64 t, %1; cvt.u32.u64 %0, t; }" : "=r"(a) : "l"(p));
    return a;
}
__device__ __forceinline__ unsigned f2key(float v) {
    unsigned u = __float_as_uint(v);
    return (u & 0x80000000u) ? ~u : (u | 0x80000000u);
}
__device__ __forceinline__ float key2f(unsigned k) {
    unsigned u = (k & 0x80000000u) ? (k & 0x7fffffffu) : ~k;
    return __uint_as_float(u);
}
__device__ __forceinline__ unsigned h2(float lo, float hi) {
    __half2 p = __floats2half2_rn(lo, hi);
    return *(unsigned*)&p;
}

#define MMA_FP16(dv, a0, a1, a2, a3, b0, b1) \
    asm volatile("mma.sync.aligned.m16n8k16.row.col.f32.f16.f16.f32 " \
        "{%0,%1,%2,%3}, {%4,%5,%6,%7}, {%8,%9}, {%0,%1,%2,%3};" \
        : "+f"((dv)[0]), "+f"((dv)[1]), "+f"((dv)[2]), "+f"((dv)[3]) \
        : "r"(a0), "r"(a1), "r"(a2), "r"(a3), "r"(b0), "r"(b1))

#define CP_ASYNC16(dst_u32, src_ptr) \
    asm volatile("cp.async.ca.shared.global [%0], [%1], 16;" :: "r"(dst_u32), "l"(src_ptr))
#define CP_COMMIT()  asm volatile("cp.async.commit_group;")
#define CP_WAIT0()   asm volatile("cp.async.wait_group 0;" ::: "memory")

__device__ __forceinline__ int a_addr(int stg, int ks, int p, int q) {
    return AS_B + ((stg * 4 + ks) * 64 + p) * 32 + q * 8;
}
__device__ __forceinline__ int b_addr(int stg, int ks, int n, int q) {
    return BS_B + ((stg * 4 + ks) * 256 + n) * 32 + q * 8;
}

// ---------------- merged prep kernel ----------------
// tap-major: k' = tap*128 + ci ; stage = k'>>6, ks = (k'>>4)&3, klocal = k'&15
__global__ void prep_all(const float* __restrict__ w) {
    __shared__ float red[128];
    int co = blockIdx.x;
    unsigned short* dst = (unsigned short*)g_wh;
    float s = 0.f;
    for (int kp = threadIdx.x; kp < 1152; kp += 128) {
        int tap = kp >> 7;
        int ci  = kp & 127;
        float v = w[co * 1152 + ci * 9 + tap];
        s += fabsf(v);
        int cstg = kp >> 6;
        int ks = (kp >> 4) & 3;
        int j = kp & 15;
        int q = (j & 7) >> 1, half = j >> 3, slot = j & 1;
        int idx = ((((cstg * 4 + ks) * COUT + co) * 4 + q) * 4) + half * 2 + slot;
        dst[idx] = __half_as_ushort(__float2half(v));
    }
    red[threadIdx.x] = s;
    __syncthreads();
    for (int off = 64; off > 0; off >>= 1) {
        if (threadIdx.x < off) red[threadIdx.x] += red[threadIdx.x + off];
        __syncthreads();
    }
    if (threadIdx.x == 0) g_wbias[co] = red[0];
}

// ---------------- main fused kernel ----------------
// CTA: 64 pixels (1 row) x 256 couts, 512 threads (16 warps), 2 CTAs/SM.
// warp (wm = wid&1, wn = wid>>1): 2 m-tiles x 4 n-tiles of m16n8k16 fp16.
__global__ void __launch_bounds__(512, 2)
conv_mma_kernel(const float* __restrict__ x, const float* __restrict__ w,
                const float* __restrict__ rbias,
                const float* __restrict__ noise, float* __restrict__ out) {
    extern __shared__ float smem[];
    char* smc = (char*)smem;
    const uint32_t smem_base = smem_to_u32(smem);
    const int t   = threadIdx.x;
    const int wid = t >> 5;
    const int lid = t & 31;
    const int g   = lid >> 2;
    const int tig = lid & 3;
    const int b   = blockIdx.y;
    const int y0  = blockIdx.x;          // one row of 64 pixels

    const int wm = wid & 1;
    const int wn = wid >> 1;

    float* rb_s = smem + RB_F;
    float* wb_s = smem + WB_F;
    unsigned* tkey_s = (unsigned*)(smem + TK_F);
    int* cnt_s = (int*)(smem + CNT_F);
    int* list_s = (int*)(smem + LIST_F);
    if (t < 256) { rb_s[t] = rbias[t]; wb_s[t] = g_wbias[t]; }
    if (t == 0) cnt_s[0] = 0;

    float d[2][4][4];
#pragma unroll
    for (int i = 0; i < 2; i++)
#pragma unroll
        for (int j = 0; j < 4; j++)
#pragma unroll
            for (int q = 0; q < 4; q++) d[i][j][q] = 0.f;

    // A-build mapping: 512 threads = 64 pixels x 4 aq x 2 ks-pairs
    const int ap  = (t >> 2) & 63;   // pixel (x coord)
    const int aq  = t & 3;           // q group
    const int ah  = t >> 8;          // ks pair: handles ks = 2ah, 2ah+1
    const float* xb = x + ((size_t)b << 19);   // b*CIN*4096

    // one 64-k stage = tap (c>>1), ci base (c&1)*64
    auto a_build_load = [&](int c, float v[8]) {
        int tap = c >> 1;
        int kh = (tap * 11) >> 5;
        int kw = tap - 3 * kh;
        int y  = y0 + kh - 1;
        int xx = ap + kw - 1;
        bool ok = ((unsigned)y < HH) && ((unsigned)xx < WW);
        const float* xp = xb + (((c & 1) * 64 + ah * 32) << 12) + (y << 6) + xx;
#pragma unroll
        for (int jj = 0; jj < 8; jj++) {
            int ksl = jj >> 2, sub = jj & 3;   // local ks, value slot
            int ci_off = (ksl << 4) + 2 * aq + (sub & 1) + (((sub >> 1) & 1) << 3);
            v[jj] = ok ? __ldg(xp + (ci_off << 12)) : 0.f;
        }
    };
    auto a_store = [&](int stg, float v[8]) {
#pragma unroll
        for (int ksl = 0; ksl < 2; ksl++) {
            *(uint2*)(smc + a_addr(stg, ah * 2 + ksl, ap, aq)) =
                make_uint2(h2(v[4*ksl+0], v[4*ksl+1]), h2(v[4*ksl+2], v[4*ksl+3]));
        }
    };

    // ---- prologue: stage 0
    {
        const char* bsrc = (const char*)g_wh;
#pragma unroll
        for (int it = 0; it < 4; it++) {
            int i = it * 512 + t;                 // 16B unit 0..2047
            CP_ASYNC16(smem_base + (uint32_t)(BS_B + i * 16), bsrc + i * 16);
        }
        CP_COMMIT();
        float v[8];
        a_build_load(0, v);
        a_store(0, v);
        CP_WAIT0();
        __syncthreads();
    }

    for (int c = 0; c < NSTG; c++) {
        const int cur = c & 1, nxt = cur ^ 1;
        const bool pf = (c < NSTG - 1);
        if (pf) {
            const char* bsrc = (const char*)(g_wh + (size_t)(c + 1) * 4 * COUT * 4);
#pragma unroll
            for (int it = 0; it < 4; it++) {
                int i = it * 512 + t;
                CP_ASYNC16(smem_base + (uint32_t)(BS_B + nxt * 32768 + i * 16), bsrc + i * 16);
            }
            CP_COMMIT();
        }
        float v[8];
        if (pf) a_build_load(c + 1, v);
        // ---- compute: 4 k16-halves, 2 m-tiles x 4 n-tiles
#pragma unroll
        for (int ks = 0; ks < 4; ks++) {
            uint2 af[2][2];
#pragma unroll
            for (int mt = 0; mt < 2; mt++) {
                int m0 = wm * 32 + mt * 16 + g;
                af[mt][0] = *(const uint2*)(smc + a_addr(cur, ks, m0,     tig));
                af[mt][1] = *(const uint2*)(smc + a_addr(cur, ks, m0 + 8, tig));
            }
#pragma unroll
            for (int nt = 0; nt < 4; nt++) {
                int n = wn * 32 + nt * 8 + g;
                uint2 bf_ = *(const uint2*)(smc + b_addr(cur, ks, n, tig));
#pragma unroll
                for (int mt = 0; mt < 2; mt++) {
                    MMA_FP16(d[mt][nt], af[mt][0].x, af[mt][1].x, af[mt][0].y, af[mt][1].y,
                             bf_.x, bf_.y);
                }
            }
        }
        if (pf) {
            a_store(nxt, v);
            CP_WAIT0();
        }
        __syncthreads();
    }

    // ---- epilogue: spill accums to o_s[p*257 + co] (scalar stores, odd stride)
    float* o_s = smem;
#pragma unroll
    for (int mt = 0; mt < 2; mt++) {
#pragma unroll
        for (int nt = 0; nt < 4; nt++) {
            int p  = wm * 32 + mt * 16 + g;
            int co = wn * 32 + nt * 8 + 2 * tig;
            o_s[p * OS_STRIDE + co]           = d[mt][nt][0];
            o_s[p * OS_STRIDE + co + 1]       = d[mt][nt][1];
            o_s[(p + 8) * OS_STRIDE + co]     = d[mt][nt][2];
            o_s[(p + 8) * OS_STRIDE + co + 1] = d[mt][nt][3];
        }
    }
    __syncthreads();

    // ---- noise inject (32 iters: 64 pix x 256 co)
#pragma unroll 4
    for (int it = 0; it < 32; it++) {
        int i  = it * 512 + t;
        int co = i >> 6;
        int p  = i & 63;
        float u = noise[((b * COUT + co) << 12) + (y0 << 6) + p];
        o_s[p * OS_STRIDE + co] += wb_s[co] * (NOISE_SCALE * (2.f * u - 1.f));
    }
    __syncthreads();

    // ---- pass 1: approx kth (bits 31..9, packed counts) + fused band collect
    for (int ii = 0; ii < 2; ii++) {
        int pa = wid * 4 + ii * 2;
        int pb = pa + 1;
        unsigned ka[8], kb[8];
#pragma unroll
        for (int m = 0; m < 8; m++) {
            ka[m] = f2key(o_s[pa * OS_STRIDE + lid + 32 * m]);
            kb[m] = f2key(o_s[pb * OS_STRIDE + lid + 32 * m]);
        }
        unsigned ra = 0u, rb2 = 0u;
        for (int bit = 31; bit >= 9; bit--) {
            unsigned ca_ = ra  | (1u << bit);
            unsigned cb_ = rb2 | (1u << bit);
            unsigned cnt = 0;
#pragma unroll
            for (int m = 0; m < 8; m++)
                cnt += (ka[m] >= ca_) + ((kb[m] >= cb_) << 16);
            cnt = __reduce_add_sync(0xffffffffu, cnt);
            if ((cnt & 0xffffu) >= KTOP) ra  = ca_;
            if ((cnt >> 16)     >= KTOP) rb2 = cb_;
        }
        if (lid == 0) { tkey_s[pa] = ra; tkey_s[pb] = rb2; }
        float tva = key2f(ra), tvb = key2f(rb2);
        unsigned kloA = f2key(tva - BAND), khiA = f2key(tva + BAND);
        unsigned kloB = f2key(tvb - BAND), khiB = f2key(tvb + BAND);
#pragma unroll
        for (int m = 0; m < 8; m++) {
            if (ka[m] >= kloA && ka[m] <= khiA) {
                int idx = atomicAdd(cnt_s, 1);
                if (idx < LISTCAP) list_s[idx] = (pa << 8) | (lid + 32 * m);
            }
            if (kb[m] >= kloB && kb[m] <= khiB) {
                int idx = atomicAdd(cnt_s, 1);
                if (idx < LISTCAP) list_s[idx] = (pb << 8) | (lid + 32 * m);
            }
        }
    }
    __syncthreads();

    // ---- exact fp32 recompute of band elements (one warp per element)
    {
        int cnt = min(cnt_s[0], LISTCAP);
        for (int e = wid; e < cnt; e += 16) {
            int pc = list_s[e];
            int p  = pc >> 8;
            int co = pc & 255;
            float acc = 0.f;
#pragma unroll
            for (int j = 0; j < 36; j++) {
                int k = lid + 32 * j;
                int ci = (k * 7282) >> 16;
                int r9 = k - 9 * ci;
                int kh = (r9 * 11) >> 5;
                int kw = r9 - 3 * kh;
                int y  = y0 + kh - 1;
                int xx = (p & 63) + kw - 1;
                float xv = ((unsigned)y < HH && (unsigned)xx < WW)
                           ? x[((b * CIN + ci) << 12) + (y << 6) + xx] : 0.f;
                acc += xv * w[co * 1152 + k];
            }
#pragma unroll
            for (int off = 16; off > 0; off >>= 1)
                acc += __shfl_xor_sync(0xffffffffu, acc, off);
            if (lid == 0) {
                float u = noise[((b * COUT + co) << 12) + (y0 << 6) + p];
                o_s[p * OS_STRIDE + co] = acc + wb_s[co] * (NOISE_SCALE * (2.f * u - 1.f));
            }
        }
    }
    __syncthreads();

    // ---- pass 2: exact kth on corrected values, prefix-narrowed to [T +/- 2*BAND]
    for (int ii = 0; ii < 2; ii++) {
        int pa = wid * 4 + ii * 2;
        int pb = pa + 1;
        float tva = key2f(tkey_s[pa]);
        float tvb = key2f(tkey_s[pb]);
        unsigned kloA = f2key(tva - 2.f * BAND), khiA = f2key(tva + 2.f * BAND);
        unsigned kloB = f2key(tvb - 2.f * BAND), khiB = f2key(tvb + 2.f * BAND);
        int hbA = 31 - __clz((kloA ^ khiA) | 1);
        int hbB = 31 - __clz((kloB ^ khiB) | 1);
        int hb  = hbA > hbB ? hbA : hbB;
        unsigned maskhi = (hb >= 31) ? 0u : ~((2u << hb) - 1u);
        unsigned ra  = kloA & maskhi;
        unsigned rb2 = kloB & maskhi;
        unsigned ka[8], kb[8];
#pragma unroll
        for (int m = 0; m < 8; m++) {
            ka[m] = f2key(o_s[pa * OS_STRIDE + lid + 32 * m]);
            kb[m] = f2key(o_s[pb * OS_STRIDE + lid + 32 * m]);
        }
        for (int bit = hb; bit >= 0; bit--) {
            unsigned ca_ = ra  | (1u << bit);
            unsigned cb_ = rb2 | (1u << bit);
            unsigned cnt = 0;
#pragma unroll
            for (int m = 0; m < 8; m++)
                cnt += (ka[m] >= ca_) + ((kb[m] >= cb_) << 16);
            cnt = __reduce_add_sync(0xffffffffu, cnt);
            if ((cnt & 0xffffu) >= KTOP) ra  = ca_;
            if ((cnt >> 16)     >= KTOP) rb2 = cb_;
        }
        if (lid == 0) { tkey_s[pa] = ra; tkey_s[pb] = rb2; }
    }
    __syncthreads();

    // ---- threshold (>= keeps ties) + relu_bias + relu, coalesced store
#pragma unroll 4
    for (int it = 0; it < 32; it++) {
        int i  = it * 512 + t;
        int co = i >> 6;
        int p  = i & 63;
        float vv = o_s[p * OS_STRIDE + co];
        float r = (f2key(vv) >= tkey_s[p]) ? vv : 0.f;
        r = fmaxf(r + rb_s[co], 0.f);
        out[((b * COUT + co) << 12) + (y0 << 6) + p] = r;
    }
}

extern "C" void kernel_launch(void* const* d_in, const int* in_sizes, int n_in,
                              void* d_out, int out_size) {
    const float* x  = (const float*)d_in[0];
    const float* w  = (const float*)d_in[1];
    const float* rb = (const float*)d_in[2];
    const float* nu = (const float*)d_in[3];
    float* out = (float*)d_out;

    cudaFuncSetAttribute(conv_mma_kernel,
                         cudaFuncAttributeMaxDynamicSharedMemorySize, SMEM_BYTES);

    prep_all<<<256, 128>>>(w);
    conv_mma_kernel<<<dim3(64, 32), 512, SMEM_BYTES>>>(x, w, rb, nu, out);
}